// round 6
// baseline (speedup 1.0000x reference)
#include <cuda_runtime.h>
#include <cuda_bf16.h>
#include <cuda_fp16.h>
#include <math.h>
#include <stdint.h>

// ---------------- problem constants ----------------
#define NL   12
#define BB   4
#define TT   1024
#define CC   768
#define HH   12
#define HS   64
#define VV   50257
#define BT   (BB * TT)
#define C3   (3 * CC)
#define C4   (4 * CC)
#define SCALE 0.125f

// ---------------- device scratch ----------------
__device__ float g_x[BT * CC];
__device__ float g_qkv[BT * C3];
__device__ __nv_bfloat16 g_ahi[BT * CC];
__device__ __nv_bfloat16 g_alo[BT * CC];
__device__ __nv_bfloat16 g_fhi[BT * C4];
__device__ __nv_bfloat16 g_flo[BT * C4];
__device__ __nv_bfloat16 g_whi[C4 * CC];
__device__ __nv_bfloat16 g_wlo[C4 * CC];
__device__ __half g_ahf[BT * CC];
__device__ __half g_tef[(size_t)VV * CC];

// ---------------- PTX helpers ----------------
__device__ __forceinline__ uint32_t smem_u32(const void* p) {
    uint32_t a;
    asm("{ .reg .u64 t; cvta.to.shared.u64 t, %1; cvt.u32.u64 %0, t; }" : "=r"(a) : "l"(p));
    return a;
}
__device__ __forceinline__ void cp16(uint32_t dst, const void* src, int sz) {
    asm volatile("cp.async.ca.shared.global [%0], [%1], 16, %2;"
                 :: "r"(dst), "l"(src), "r"(sz) : "memory");
}
__device__ __forceinline__ void cp_commit() {
    asm volatile("cp.async.commit_group;" ::: "memory");
}
__device__ __forceinline__ void ldsm4(uint32_t* r, uint32_t a) {
    asm volatile("ldmatrix.sync.aligned.m8n8.x4.shared.b16 {%0,%1,%2,%3}, [%4];"
                 : "=r"(r[0]), "=r"(r[1]), "=r"(r[2]), "=r"(r[3]) : "r"(a));
}
__device__ __forceinline__ void mma_bf16(float* d, const uint32_t* a,
                                         uint32_t b0, uint32_t b1) {
    asm volatile(
        "mma.sync.aligned.m16n8k16.row.col.f32.bf16.bf16.f32 "
        "{%0,%1,%2,%3}, {%4,%5,%6,%7}, {%8,%9}, {%0,%1,%2,%3};"
        : "+f"(d[0]), "+f"(d[1]), "+f"(d[2]), "+f"(d[3])
        : "r"(a[0]), "r"(a[1]), "r"(a[2]), "r"(a[3]), "r"(b0), "r"(b1));
}
__device__ __forceinline__ void mma_fp16(float* d, const uint32_t* a,
                                         uint32_t b0, uint32_t b1) {
    asm volatile(
        "mma.sync.aligned.m16n8k16.row.col.f32.f16.f16.f32 "
        "{%0,%1,%2,%3}, {%4,%5,%6,%7}, {%8,%9}, {%0,%1,%2,%3};"
        : "+f"(d[0]), "+f"(d[1]), "+f"(d[2]), "+f"(d[3])
        : "r"(a[0]), "r"(a[1]), "r"(a[2]), "r"(a[3]), "r"(b0), "r"(b1));
}
__device__ __forceinline__ uint32_t packbf(float a, float b) {
    __nv_bfloat162 t = __floats2bfloat162_rn(a, b);
    return *reinterpret_cast<uint32_t*>(&t);
}
__device__ __forceinline__ float bfhi(float v) {
    return __bfloat162float(__float2bfloat16(v));
}

// ---------------- embedding ----------------
__global__ void embed_kernel(const int* __restrict__ inp,
                             const float* __restrict__ wte,
                             const float* __restrict__ wpe,
                             float* __restrict__ x) {
    int i = blockIdx.x * blockDim.x + threadIdx.x;
    if (i >= BT * CC) return;
    int c = i % CC;
    int bt = i / CC;
    int t = bt % TT;
    int tok = inp[bt];
    x[i] = wte[(size_t)tok * CC + c] + wpe[(size_t)t * CC + c];
}

// ---------------- layernorm (warp per row) -> bf16 hi/lo ----------------
__global__ void __launch_bounds__(256)
ln_hl_kernel(const float* __restrict__ in,
             const float* __restrict__ g,
             const float* __restrict__ b,
             __nv_bfloat16* __restrict__ hi,
             __nv_bfloat16* __restrict__ lo) {
    int row = blockIdx.x * 8 + (threadIdx.x >> 5);
    int lane = threadIdx.x & 31;
    const float4* r4 = (const float4*)(in + (size_t)row * CC);

    float4 v[6];
    float s = 0.f;
    #pragma unroll
    for (int i = 0; i < 6; i++) {
        v[i] = r4[lane + i * 32];
        s += v[i].x + v[i].y + v[i].z + v[i].w;
    }
    #pragma unroll
    for (int o = 16; o > 0; o >>= 1) s += __shfl_xor_sync(0xffffffffu, s, o);
    float mu = s / CC;

    float sq = 0.f;
    #pragma unroll
    for (int i = 0; i < 6; i++) {
        float dx = v[i].x - mu, dy = v[i].y - mu, dz = v[i].z - mu, dw = v[i].w - mu;
        sq += dx * dx + dy * dy + dz * dz + dw * dw;
    }
    #pragma unroll
    for (int o = 16; o > 0; o >>= 1) sq += __shfl_xor_sync(0xffffffffu, sq, o);
    float rstd = rsqrtf(sq / CC + 1e-5f);

    const float4* g4 = (const float4*)g;
    const float4* b4 = (const float4*)b;
    uint2* h2 = (uint2*)(hi + (size_t)row * CC);
    uint2* l2 = (uint2*)(lo + (size_t)row * CC);
    #pragma unroll
    for (int i = 0; i < 6; i++) {
        int f4 = lane + i * 32;
        float4 gv = g4[f4], bv = b4[f4];
        float o0 = (v[i].x - mu) * rstd * gv.x + bv.x;
        float o1 = (v[i].y - mu) * rstd * gv.y + bv.y;
        float o2 = (v[i].z - mu) * rstd * gv.z + bv.z;
        float o3 = (v[i].w - mu) * rstd * gv.w + bv.w;
        uint2 hw, lw;
        hw.x = packbf(o0, o1); hw.y = packbf(o2, o3);
        lw.x = packbf(o0 - bfhi(o0), o1 - bfhi(o1));
        lw.y = packbf(o2 - bfhi(o2), o3 - bfhi(o3));
        h2[f4] = hw;
        l2[f4] = lw;
    }
}

// ---------------- final layernorm (warp per row) -> fp16 ----------------
__global__ void __launch_bounds__(256)
ln_hf_kernel(const float* __restrict__ in,
             const float* __restrict__ g,
             const float* __restrict__ b,
             __half* __restrict__ out) {
    int row = blockIdx.x * 8 + (threadIdx.x >> 5);
    int lane = threadIdx.x & 31;
    const float4* r4 = (const float4*)(in + (size_t)row * CC);

    float4 v[6];
    float s = 0.f;
    #pragma unroll
    for (int i = 0; i < 6; i++) {
        v[i] = r4[lane + i * 32];
        s += v[i].x + v[i].y + v[i].z + v[i].w;
    }
    #pragma unroll
    for (int o = 16; o > 0; o >>= 1) s += __shfl_xor_sync(0xffffffffu, s, o);
    float mu = s / CC;

    float sq = 0.f;
    #pragma unroll
    for (int i = 0; i < 6; i++) {
        float dx = v[i].x - mu, dy = v[i].y - mu, dz = v[i].z - mu, dw = v[i].w - mu;
        sq += dx * dx + dy * dy + dz * dz + dw * dw;
    }
    #pragma unroll
    for (int o = 16; o > 0; o >>= 1) sq += __shfl_xor_sync(0xffffffffu, sq, o);
    float rstd = rsqrtf(sq / CC + 1e-5f);

    const float4* g4 = (const float4*)g;
    const float4* b4 = (const float4*)b;
    uint2* o2p = (uint2*)(out + (size_t)row * CC);
    #pragma unroll
    for (int i = 0; i < 6; i++) {
        int f4 = lane + i * 32;
        float4 gv = g4[f4], bv = b4[f4];
        float o0 = (v[i].x - mu) * rstd * gv.x + bv.x;
        float o1 = (v[i].y - mu) * rstd * gv.y + bv.y;
        float o2 = (v[i].z - mu) * rstd * gv.z + bv.z;
        float o3 = (v[i].w - mu) * rstd * gv.w + bv.w;
        __half2 p0 = __floats2half2_rn(o0, o1);
        __half2 p1 = __floats2half2_rn(o2, o3);
        uint2 w;
        w.x = *(uint32_t*)&p0; w.y = *(uint32_t*)&p1;
        o2p[f4] = w;
    }
}

// ---------------- flash attention (bf16x3 mma, online softmax) ----------------
#define FA_STRIDE 144
#define FA_TILE   (64 * FA_STRIDE)
#define FA_SMEM   (6 * FA_TILE)

__global__ void __launch_bounds__(128, 3)
fattn_kernel(const float* __restrict__ qkv,
             __nv_bfloat16* __restrict__ ohi,
             __nv_bfloat16* __restrict__ olo) {
    extern __shared__ char fs[];
    uint32_t sb = smem_u32(fs);
    int qt = 15 - blockIdx.x;
    int bh = blockIdx.y;
    int h = bh % HH, b = bh / HH;
    int tid = threadIdx.x, lane = tid & 31, w = tid >> 5;
    int q0 = qt * 64;
    const float* base = qkv + (size_t)b * TT * C3 + (size_t)h * 3 * HS;

    {
        int r = tid >> 1, c0 = (tid & 1) * 32;
        const float* src = base + (size_t)(q0 + r) * C3 + c0;
        char* dh = fs + 0 * FA_TILE + r * FA_STRIDE + c0 * 2;
        char* dl = fs + 1 * FA_TILE + r * FA_STRIDE + c0 * 2;
        #pragma unroll
        for (int i = 0; i < 32; i += 4) {
            float4 v = *(const float4*)(src + i);
            float hx = bfhi(v.x), hy = bfhi(v.y), hz = bfhi(v.z), hw = bfhi(v.w);
            *(uint32_t*)(dh + i * 2)     = packbf(v.x, v.y);
            *(uint32_t*)(dh + i * 2 + 4) = packbf(v.z, v.w);
            *(uint32_t*)(dl + i * 2)     = packbf(v.x - hx, v.y - hy);
            *(uint32_t*)(dl + i * 2 + 4) = packbf(v.z - hz, v.w - hw);
        }
    }
    __syncthreads();

    int lr = lane & 15, lh = (lane >> 4) * 16;
    uint32_t qh[4][4], ql[4][4];
    #pragma unroll
    for (int kk = 0; kk < 4; kk++) {
        uint32_t ad = sb + 0 * FA_TILE + (uint32_t)(w * 16 + lr) * FA_STRIDE + kk * 32 + lh;
        ldsm4(qh[kk], ad);
        ldsm4(ql[kk], ad + FA_TILE);
    }

    int g = lane >> 2, tg = lane & 3;
    int r0 = q0 + w * 16 + g;
    float m0 = -1e30f, m1 = -1e30f, l0 = 0.f, l1 = 0.f;
    float O[8][4];
    #pragma unroll
    for (int f = 0; f < 8; f++)
        #pragma unroll
        for (int e = 0; e < 4; e++) O[f][e] = 0.f;

    for (int kt = 0; kt <= qt; kt++) {
        __syncthreads();
        {
            int r = tid >> 1, c0 = (tid & 1) * 32;
            const float* ks = base + (size_t)(kt * 64 + r) * C3 + HS + c0;
            const float* vs = base + (size_t)(kt * 64 + r) * C3 + 2 * HS + c0;
            char* kh = fs + 2 * FA_TILE + r * FA_STRIDE + c0 * 2;
            char* kl = fs + 3 * FA_TILE + r * FA_STRIDE + c0 * 2;
            #pragma unroll
            for (int i = 0; i < 32; i += 4) {
                float4 v = *(const float4*)(ks + i);
                float hx = bfhi(v.x), hy = bfhi(v.y), hz = bfhi(v.z), hw = bfhi(v.w);
                *(uint32_t*)(kh + i * 2)     = packbf(v.x, v.y);
                *(uint32_t*)(kh + i * 2 + 4) = packbf(v.z, v.w);
                *(uint32_t*)(kl + i * 2)     = packbf(v.x - hx, v.y - hy);
                *(uint32_t*)(kl + i * 2 + 4) = packbf(v.z - hz, v.w - hw);
            }
            #pragma unroll
            for (int i = 0; i < 32; i++) {
                float v = vs[i];
                float hv = bfhi(v);
                int d = c0 + i;
                *(__nv_bfloat16*)(fs + 4 * FA_TILE + d * FA_STRIDE + r * 2) = __float2bfloat16(v);
                *(__nv_bfloat16*)(fs + 5 * FA_TILE + d * FA_STRIDE + r * 2) = __float2bfloat16(v - hv);
            }
        }
        __syncthreads();

        float S[8][4];
        #pragma unroll
        for (int f = 0; f < 8; f++)
            #pragma unroll
            for (int e = 0; e < 4; e++) S[f][e] = 0.f;

        #pragma unroll
        for (int kk = 0; kk < 4; kk++) {
            #pragma unroll
            for (int nt = 0; nt < 4; nt++) {
                uint32_t bd = sb + 2 * FA_TILE + (uint32_t)(nt * 16 + lr) * FA_STRIDE + kk * 32 + lh;
                uint32_t bhf[4], blf[4];
                ldsm4(bhf, bd);
                ldsm4(blf, bd + FA_TILE);
                #pragma unroll
                for (int sub = 0; sub < 2; sub++) {
                    float* d = S[nt * 2 + sub];
                    mma_bf16(d, qh[kk], bhf[sub], bhf[sub + 2]);
                    mma_bf16(d, qh[kk], blf[sub], blf[sub + 2]);
                    mma_bf16(d, ql[kk], bhf[sub], bhf[sub + 2]);
                }
            }
        }

        #pragma unroll
        for (int f = 0; f < 8; f++)
            #pragma unroll
            for (int e = 0; e < 4; e++) S[f][e] *= SCALE;
        if (kt == qt) {
            #pragma unroll
            for (int f = 0; f < 8; f++) {
                int colb = kt * 64 + f * 8 + tg * 2;
                if (colb     > r0)     S[f][0] = -1e30f;
                if (colb + 1 > r0)     S[f][1] = -1e30f;
                if (colb     > r0 + 8) S[f][2] = -1e30f;
                if (colb + 1 > r0 + 8) S[f][3] = -1e30f;
            }
        }

        float mx0 = -1e30f, mx1 = -1e30f;
        #pragma unroll
        for (int f = 0; f < 8; f++) {
            mx0 = fmaxf(mx0, fmaxf(S[f][0], S[f][1]));
            mx1 = fmaxf(mx1, fmaxf(S[f][2], S[f][3]));
        }
        mx0 = fmaxf(mx0, __shfl_xor_sync(0xffffffffu, mx0, 1));
        mx0 = fmaxf(mx0, __shfl_xor_sync(0xffffffffu, mx0, 2));
        mx1 = fmaxf(mx1, __shfl_xor_sync(0xffffffffu, mx1, 1));
        mx1 = fmaxf(mx1, __shfl_xor_sync(0xffffffffu, mx1, 2));

        float mn0 = fmaxf(m0, mx0), mn1 = fmaxf(m1, mx1);
        float sc0 = __expf(m0 - mn0), sc1 = __expf(m1 - mn1);
        m0 = mn0; m1 = mn1;
        l0 *= sc0; l1 *= sc1;
        #pragma unroll
        for (int f = 0; f < 8; f++) {
            O[f][0] *= sc0; O[f][1] *= sc0;
            O[f][2] *= sc1; O[f][3] *= sc1;
        }

        float ps0 = 0.f, ps1 = 0.f;
        #pragma unroll
        for (int f = 0; f < 8; f++) {
            S[f][0] = __expf(S[f][0] - m0);
            S[f][1] = __expf(S[f][1] - m0);
            S[f][2] = __expf(S[f][2] - m1);
            S[f][3] = __expf(S[f][3] - m1);
            ps0 += S[f][0] + S[f][1];
            ps1 += S[f][2] + S[f][3];
        }
        ps0 += __shfl_xor_sync(0xffffffffu, ps0, 1);
        ps0 += __shfl_xor_sync(0xffffffffu, ps0, 2);
        ps1 += __shfl_xor_sync(0xffffffffu, ps1, 1);
        ps1 += __shfl_xor_sync(0xffffffffu, ps1, 2);
        l0 += ps0; l1 += ps1;

        uint32_t ph[4][4], pl[4][4];
        #pragma unroll
        for (int kk = 0; kk < 4; kk++) {
            float* A0 = S[2 * kk];
            float* A1 = S[2 * kk + 1];
            ph[kk][0] = packbf(A0[0], A0[1]);
            ph[kk][1] = packbf(A0[2], A0[3]);
            ph[kk][2] = packbf(A1[0], A1[1]);
            ph[kk][3] = packbf(A1[2], A1[3]);
            pl[kk][0] = packbf(A0[0] - bfhi(A0[0]), A0[1] - bfhi(A0[1]));
            pl[kk][1] = packbf(A0[2] - bfhi(A0[2]), A0[3] - bfhi(A0[3]));
            pl[kk][2] = packbf(A1[0] - bfhi(A1[0]), A1[1] - bfhi(A1[1]));
            pl[kk][3] = packbf(A1[2] - bfhi(A1[2]), A1[3] - bfhi(A1[3]));
        }

        #pragma unroll
        for (int kk = 0; kk < 4; kk++) {
            #pragma unroll
            for (int nt = 0; nt < 4; nt++) {
                uint32_t bd = sb + 4 * FA_TILE + (uint32_t)(nt * 16 + lr) * FA_STRIDE + kk * 32 + lh;
                uint32_t bhf[4], blf[4];
                ldsm4(bhf, bd);
                ldsm4(blf, bd + FA_TILE);
                #pragma unroll
                for (int sub = 0; sub < 2; sub++) {
                    float* d = O[nt * 2 + sub];
                    mma_bf16(d, ph[kk], bhf[sub], bhf[sub + 2]);
                    mma_bf16(d, ph[kk], blf[sub], blf[sub + 2]);
                    mma_bf16(d, pl[kk], bhf[sub], bhf[sub + 2]);
                }
            }
        }
    }

    float inv0 = 1.f / l0, inv1 = 1.f / l1;
    #pragma unroll
    for (int f = 0; f < 8; f++) {
        int col = h * HS + f * 8 + tg * 2;
        size_t i0 = ((size_t)(b * TT + r0)) * CC + col;
        size_t i1 = i0 + (size_t)8 * CC;
        float v00 = O[f][0] * inv0, v01 = O[f][1] * inv0;
        float v10 = O[f][2] * inv1, v11 = O[f][3] * inv1;
        __nv_bfloat16 h00 = __float2bfloat16(v00);
        __nv_bfloat16 h01 = __float2bfloat16(v01);
        __nv_bfloat16 h10 = __float2bfloat16(v10);
        __nv_bfloat16 h11 = __float2bfloat16(v11);
        ohi[i0]     = h00; olo[i0]     = __float2bfloat16(v00 - __bfloat162float(h00));
        ohi[i0 + 1] = h01; olo[i0 + 1] = __float2bfloat16(v01 - __bfloat162float(h01));
        ohi[i1]     = h10; olo[i1]     = __float2bfloat16(v10 - __bfloat162float(h10));
        ohi[i1 + 1] = h11; olo[i1 + 1] = __float2bfloat16(v11 - __bfloat162float(h11));
    }
}

// ---------------- weight transpose + hi/lo split ----------------
__global__ void conv_wt_kernel(const float* __restrict__ W,
                               __nv_bfloat16* __restrict__ hi,
                               __nv_bfloat16* __restrict__ lo,
                               int K, int N) {
    __shared__ float ts[32][33];
    int k0 = blockIdx.y * 32, n0 = blockIdx.x * 32;
    int tx = threadIdx.x, ty = threadIdx.y;
    #pragma unroll
    for (int i = 0; i < 32; i += 8)
        ts[ty + i][tx] = W[(size_t)(k0 + ty + i) * N + n0 + tx];
    __syncthreads();
    #pragma unroll
    for (int i = 0; i < 32; i += 8) {
        float v = ts[tx][ty + i];
        size_t o = (size_t)(n0 + ty + i) * K + k0 + tx;
        __nv_bfloat16 h = __float2bfloat16(v);
        hi[o] = h;
        lo[o] = __float2bfloat16(v - __bfloat162float(h));
    }
}

// ---------------- wte -> fp16 ----------------
__global__ void conv_hf_kernel(const float* __restrict__ x,
                               __half* __restrict__ out, size_t n) {
    size_t i = (size_t)blockIdx.x * blockDim.x + threadIdx.x;
    if (i < n) out[i] = __float2half(x[i]);
}

// ---------------- HMMA bf16x3 GEMM (internal layers) ----------------
// CTA 128x128, 4 warps (2x2), warp tile 64x64, K-step 32, double buffer.
#define TSTRIDE  80
#define T_A_HI   0
#define T_A_LO   10240
#define T_B_HI   20480
#define T_B_LO   30720
#define T_STAGE  40960
#define GSMEM    (2 * T_STAGE)

template<bool BIAS, bool GELU, bool RES, bool OUTHL>
__global__ void __launch_bounds__(128, 2)
gemm3_kernel(const __nv_bfloat16* __restrict__ Ahi, const __nv_bfloat16* __restrict__ Alo,
             const __nv_bfloat16* __restrict__ Bhi, const __nv_bfloat16* __restrict__ Blo,
             const float* __restrict__ bias, const float* __restrict__ res,
             float* __restrict__ C,
             __nv_bfloat16* __restrict__ Chi, __nv_bfloat16* __restrict__ Clo,
             int M, int N, int K) {
    extern __shared__ char smem[];
    uint32_t sb = smem_u32(smem);
    int tid = threadIdx.x;
    int lane = tid & 31, wid = tid >> 5;
    int wr = wid >> 1, wc = wid & 1;       // 2x2 warps, warp tile 64x64
    int row0 = blockIdx.y * 128, col0 = blockIdx.x * 128;

    const char* pAhi = (const char*)Ahi;
    const char* pAlo = (const char*)Alo;
    const char* pBhi = (const char*)Bhi;
    const char* pBlo = (const char*)Blo;

    float acc[4][8][4];
    #pragma unroll
    for (int a = 0; a < 4; a++)
        #pragma unroll
        for (int b = 0; b < 8; b++)
            #pragma unroll
            for (int e = 0; e < 4; e++) acc[a][b][e] = 0.f;

    int nc = K / 32;
    size_t Kb = (size_t)K * 2;

    // loader: 128 threads, thread t owns row t (one full 64B row per tile)
    int lrow = tid;
    size_t a_row = (size_t)(row0 + lrow) * Kb;
    int nr = col0 + lrow;
    bool bval = nr < N;
    size_t b_row = (size_t)(bval ? nr : 0) * Kb;
    uint32_t so = (uint32_t)lrow * TSTRIDE;

    auto load_tile = [&](int c) {
        uint32_t s = sb + (uint32_t)(c & 1) * T_STAGE;
        size_t kb = (size_t)c * 64;
        #pragma unroll
        for (int p = 0; p < 4; p++) {
            cp16(s + T_A_HI + so + p * 16, pAhi + a_row + kb + p * 16, 16);
            cp16(s + T_A_LO + so + p * 16, pAlo + a_row + kb + p * 16, 16);
            int v = bval ? 16 : 0;
            cp16(s + T_B_HI + so + p * 16, pBhi + b_row + kb + p * 16, v);
            cp16(s + T_B_LO + so + p * 16, pBlo + b_row + kb + p * 16, v);
        }
        cp_commit();
    };

    load_tile(0);

    int lr = lane & 15;
    int lh = (lane >> 4) * 16;

    for (int c = 0; c < nc; c++) {
        if (c + 1 < nc) {
            load_tile(c + 1);
            asm volatile("cp.async.wait_group 1;" ::: "memory");
        } else {
            asm volatile("cp.async.wait_group 0;" ::: "memory");
        }
        __syncthreads();

        uint32_t s = sb + (uint32_t)(c & 1) * T_STAGE;
        #pragma unroll
        for (int ks = 0; ks < 2; ks++) {
            uint32_t ko = ks * 32;
            uint32_t ah[4][4], al[4][4];
            #pragma unroll
            for (int mt = 0; mt < 4; mt++) {
                uint32_t ad = s + T_A_HI +
                              (uint32_t)(wr * 64 + mt * 16 + lr) * TSTRIDE + ko + lh;
                ldsm4(ah[mt], ad);
                ldsm4(al[mt], ad + (T_A_LO - T_A_HI));
            }
            #pragma unroll
            for (int nt = 0; nt < 4; nt++) {
                uint32_t bd = s + T_B_HI +
                              (uint32_t)(wc * 64 + nt * 16 + lr) * TSTRIDE + ko + lh;
                uint32_t bh[4], bl[4];
                ldsm4(bh, bd);
                ldsm4(bl, bd + (T_B_LO - T_B_HI));
                #pragma unroll
                for (int mt = 0; mt < 4; mt++) {
                    #pragma unroll
                    for (int sub = 0; sub < 2; sub++) {
                        float* d = acc[mt][nt * 2 + sub];
                        mma_bf16(d, ah[mt], bh[sub], bh[sub + 2]);
                        mma_bf16(d, ah[mt], bl[sub], bl[sub + 2]);
                        mma_bf16(d, al[mt], bh[sub], bh[sub + 2]);
                    }
                }
            }
        }
        __syncthreads();
    }

    int g = lane >> 2, tg = lane & 3;
    #pragma unroll
    for (int mt = 0; mt < 4; mt++) {
        int r0g = row0 + wr * 64 + mt * 16 + g;
        #pragma unroll
        for (int n8 = 0; n8 < 8; n8++) {
            int gc = col0 + wc * 64 + n8 * 8 + tg * 2;
            float* d = acc[mt][n8];
            #pragma unroll
            for (int e = 0; e < 4; e++) {
                int rr = r0g + ((e >= 2) ? 8 : 0);
                int cc_ = gc + (e & 1);
                if (cc_ < N) {
                    float v = d[e];
                    if (BIAS) v += bias[cc_];
                    if (GELU) v = 0.5f * v * (1.0f + erff(v * 0.7071067811865475f));
                    if (RES)  v += res[(size_t)rr * N + cc_];
                    size_t idx = (size_t)rr * N + cc_;
                    if (OUTHL) {
                        __nv_bfloat16 hv = __float2bfloat16(v);
                        Chi[idx] = hv;
                        Clo[idx] = __float2bfloat16(v - __bfloat162float(hv));
                    } else {
                        C[idx] = v;
                    }
                }
            }
        }
    }
}

// ---------------- HMMA fp16 GEMM (LM head), warp tile 64x64 ----------------
#define H_A      0
#define H_B      10240
#define H_STAGE  20480
#define GSMEMH   (2 * H_STAGE)

__global__ void __launch_bounds__(128, 2)
gemmh_kernel(const __half* __restrict__ A, const __half* __restrict__ B,
             float* __restrict__ C, int M, int N, int K) {
    extern __shared__ char smem[];
    uint32_t sb = smem_u32(smem);
    int tid = threadIdx.x;
    int lane = tid & 31, wid = tid >> 5;
    int wr = wid >> 1, wc = wid & 1;
    int row0 = blockIdx.y * 128, col0 = blockIdx.x * 128;

    const char* pA = (const char*)A;
    const char* pB = (const char*)B;

    float acc[4][8][4];
    #pragma unroll
    for (int a = 0; a < 4; a++)
        #pragma unroll
        for (int b = 0; b < 8; b++)
            #pragma unroll
            for (int e = 0; e < 4; e++) acc[a][b][e] = 0.f;

    int nc = K / 32;
    size_t Kb = (size_t)K * 2;
    int lrow = tid;
    size_t a_row = (size_t)(row0 + lrow) * Kb;
    int nr = col0 + lrow;
    bool bval = nr < N;
    size_t b_row = (size_t)(bval ? nr : 0) * Kb;
    uint32_t so = (uint32_t)lrow * TSTRIDE;

    auto load_tile = [&](int c) {
        uint32_t s = sb + (uint32_t)(c & 1) * H_STAGE;
        size_t kb = (size_t)c * 64;
        #pragma unroll
        for (int p = 0; p < 4; p++) {
            cp16(s + H_A + so + p * 16, pA + a_row + kb + p * 16, 16);
            int v = bval ? 16 : 0;
            cp16(s + H_B + so + p * 16, pB + b_row + kb + p * 16, v);
        }
        cp_commit();
    };

    load_tile(0);

    int lr = lane & 15;
    int lh = (lane >> 4) * 16;

    for (int c = 0; c < nc; c++) {
        if (c + 1 < nc) {
            load_tile(c + 1);
            asm volatile("cp.async.wait_group 1;" ::: "memory");
        } else {
            asm volatile("cp.async.wait_group 0;" ::: "memory");
        }
        __syncthreads();

        uint32_t s = sb + (uint32_t)(c & 1) * H_STAGE;
        #pragma unroll
        for (int ks = 0; ks < 2; ks++) {
            uint32_t ko = ks * 32;
            uint32_t ah[4][4];
            #pragma unroll
            for (int mt = 0; mt < 4; mt++) {
                uint32_t ad = s + H_A +
                              (uint32_t)(wr * 64 + mt * 16 + lr) * TSTRIDE + ko + lh;
                ldsm4(ah[mt], ad);
            }
            #pragma unroll
            for (int nt = 0; nt < 4; nt++) {
                uint32_t bd = s + H_B +
                              (uint32_t)(wc * 64 + nt * 16 + lr) * TSTRIDE + ko + lh;
                uint32_t bf[4];
                ldsm4(bf, bd);
                #pragma unroll
                for (int mt = 0; mt < 4; mt++) {
                    #pragma unroll
                    for (int sub = 0; sub < 2; sub++)
                        mma_fp16(acc[mt][nt * 2 + sub], ah[mt], bf[sub], bf[sub + 2]);
                }
            }
        }
        __syncthreads();
    }

    int g = lane >> 2, tg = lane & 3;
    #pragma unroll
    for (int mt = 0; mt < 4; mt++) {
        int r0g = row0 + wr * 64 + mt * 16 + g;
        #pragma unroll
        for (int n8 = 0; n8 < 8; n8++) {
            int gc = col0 + wc * 64 + n8 * 8 + tg * 2;
            float* d = acc[mt][n8];
            #pragma unroll
            for (int e = 0; e < 4; e++) {
                int rr = r0g + ((e >= 2) ? 8 : 0);
                int cc_ = gc + (e & 1);
                if (cc_ < N) C[(size_t)rr * N + cc_] = d[e];
            }
        }
    }
}

// ---------------- host orchestration ----------------
static void conv_wT(const float* W, __nv_bfloat16* hi, __nv_bfloat16* lo, int K, int N) {
    conv_wt_kernel<<<dim3(N / 32, K / 32), dim3(32, 8)>>>(W, hi, lo, K, N);
}

template<bool BIAS, bool GELU, bool RES, bool OUTHL>
static void gemm3(const __nv_bfloat16* ahi, const __nv_bfloat16* alo,
                  const __nv_bfloat16* bhi, const __nv_bfloat16* blo,
                  const float* bias, const float* res,
                  float* C, __nv_bfloat16* Chi, __nv_bfloat16* Clo,
                  int M, int N, int K) {
    dim3 grid((N + 127) / 128, M / 128);
    gemm3_kernel<BIAS, GELU, RES, OUTHL><<<grid, 128, GSMEM>>>(
        ahi, alo, bhi, blo, bias, res, C, Chi, Clo, M, N, K);
}

extern "C" void kernel_launch(void* const* d_in, const int* in_sizes, int n_in,
                              void* d_out, int out_size) {
    const int*   inp   = (const int*)  d_in[0];
    const float* wte   = (const float*)d_in[1];
    const float* wpe   = (const float*)d_in[2];
    const float* ln1_g = (const float*)d_in[3];
    const float* ln1_b = (const float*)d_in[4];
    const float* wqkv  = (const float*)d_in[5];
    const float* bqkv  = (const float*)d_in[6];
    const float* wout  = (const float*)d_in[7];
    const float* bout  = (const float*)d_in[8];
    const float* ln2_g = (const float*)d_in[9];
    const float* ln2_b = (const float*)d_in[10];
    const float* wfc1  = (const float*)d_in[11];
    const float* bfc1  = (const float*)d_in[12];
    const float* wfc2  = (const float*)d_in[13];
    const float* bfc2  = (const float*)d_in[14];
    const float* lnf_g = (const float*)d_in[15];
    const float* lnf_b = (const float*)d_in[16];
    float* logits = (float*)d_out;

    float *x, *qkv;
    __nv_bfloat16 *ahi, *alo, *fhi, *flo, *whi, *wlo;
    __half *ahf, *tef;
    cudaGetSymbolAddress((void**)&x,   g_x);
    cudaGetSymbolAddress((void**)&qkv, g_qkv);
    cudaGetSymbolAddress((void**)&ahi, g_ahi);
    cudaGetSymbolAddress((void**)&alo, g_alo);
    cudaGetSymbolAddress((void**)&fhi, g_fhi);
    cudaGetSymbolAddress((void**)&flo, g_flo);
    cudaGetSymbolAddress((void**)&whi, g_whi);
    cudaGetSymbolAddress((void**)&wlo, g_wlo);
    cudaGetSymbolAddress((void**)&ahf, g_ahf);
    cudaGetSymbolAddress((void**)&tef, g_tef);

    cudaFuncSetAttribute(gemm3_kernel<true,  false, false, false>, cudaFuncAttributeMaxDynamicSharedMemorySize, GSMEM);
    cudaFuncSetAttribute(gemm3_kernel<true,  false, true,  false>, cudaFuncAttributeMaxDynamicSharedMemorySize, GSMEM);
    cudaFuncSetAttribute(gemm3_kernel<true,  true,  false, true >, cudaFuncAttributeMaxDynamicSharedMemorySize, GSMEM);
    cudaFuncSetAttribute(gemmh_kernel, cudaFuncAttributeMaxDynamicSharedMemorySize, GSMEMH);
    cudaFuncSetAttribute(fattn_kernel, cudaFuncAttributeMaxDynamicSharedMemorySize, FA_SMEM);

    embed_kernel<<<(BT * CC + 255) / 256, 256>>>(inp, wte, wpe, x);

    for (int l = 0; l < NL; l++) {
        const float* g1  = ln1_g + (size_t)l * CC;
        const float* b1  = ln1_b + (size_t)l * CC;
        const float* wq  = wqkv  + (size_t)l * CC * C3;
        const float* bq  = bqkv  + (size_t)l * C3;
        const float* wo  = wout  + (size_t)l * CC * CC;
        const float* bo  = bout  + (size_t)l * CC;
        const float* g2  = ln2_g + (size_t)l * CC;
        const float* b2  = ln2_b + (size_t)l * CC;
        const float* w1  = wfc1  + (size_t)l * CC * C4;
        const float* bb1 = bfc1  + (size_t)l * C4;
        const float* w2  = wfc2  + (size_t)l * C4 * CC;
        const float* bb2 = bfc2  + (size_t)l * CC;

        ln_hl_kernel<<<BT / 8, 256>>>(x, g1, b1, ahi, alo);
        conv_wT(wq, whi, wlo, CC, C3);
        gemm3<true, false, false, false>(ahi, alo, whi, wlo, bq, nullptr,
                                         qkv, nullptr, nullptr, BT, C3, CC);

        fattn_kernel<<<dim3(16, BB * HH), 128, FA_SMEM>>>(qkv, ahi, alo);

        conv_wT(wo, whi, wlo, CC, CC);
        gemm3<true, false, true, false>(ahi, alo, whi, wlo, bo, x,
                                        x, nullptr, nullptr, BT, CC, CC);

        ln_hl_kernel<<<BT / 8, 256>>>(x, g2, b2, ahi, alo);
        conv_wT(w1, whi, wlo, CC, C4);
        gemm3<true, true, false, true>(ahi, alo, whi, wlo, bb1, nullptr,
                                       nullptr, fhi, flo, BT, C4, CC);

        conv_wT(w2, whi, wlo, C4, CC);
        gemm3<true, false, true, false>(fhi, flo, whi, wlo, bb2, x,
                                        x, nullptr, nullptr, BT, CC, C4);
    }

    ln_hf_kernel<<<BT / 8, 256>>>(x, lnf_g, lnf_b, ahf);
    conv_hf_kernel<<<(unsigned)(((size_t)VV * CC + 255) / 256), 256>>>(
        wte, tef, (size_t)VV * CC);
    {
        dim3 grid((VV + 127) / 128, BT / 128);
        gemmh_kernel<<<grid, 128, GSMEMH>>>(ahf, tef, logits, BT, VV, CC);
    }
}

// round 7
// speedup vs baseline: 1.5574x; 1.5574x over previous
#include <cuda_runtime.h>
#include <cuda_bf16.h>
#include <cuda_fp16.h>
#include <math.h>
#include <stdint.h>

// ---------------- problem constants ----------------
#define NL   12
#define BB   4
#define TT   1024
#define CC   768
#define HH   12
#define HS   64
#define VV   50257
#define BT   (BB * TT)
#define C3   (3 * CC)
#define C4   (4 * CC)
#define SCALE 0.125f

// ---------------- device scratch ----------------
__device__ float g_x[BT * CC];
__device__ __nv_bfloat16 g_qhi[BT * C3];   // qkv hi
__device__ __nv_bfloat16 g_qlo[BT * C3];   // qkv lo
__device__ __nv_bfloat16 g_ahi[BT * CC];
__device__ __nv_bfloat16 g_alo[BT * CC];
__device__ __nv_bfloat16 g_fhi[BT * C4];
__device__ __nv_bfloat16 g_flo[BT * C4];
__device__ __nv_bfloat16 g_whi[C4 * CC];
__device__ __nv_bfloat16 g_wlo[C4 * CC];
__device__ __half g_ahf[BT * CC];
__device__ __half g_tef[(size_t)VV * CC];

// ---------------- PTX helpers ----------------
__device__ __forceinline__ uint32_t smem_u32(const void* p) {
    uint32_t a;
    asm("{ .reg .u64 t; cvta.to.shared.u64 t, %1; cvt.u32.u64 %0, t; }" : "=r"(a) : "l"(p));
    return a;
}
__device__ __forceinline__ void cp16(uint32_t dst, const void* src, int sz) {
    asm volatile("cp.async.ca.shared.global [%0], [%1], 16, %2;"
                 :: "r"(dst), "l"(src), "r"(sz) : "memory");
}
__device__ __forceinline__ void cp_commit() {
    asm volatile("cp.async.commit_group;" ::: "memory");
}
__device__ __forceinline__ void ldsm4(uint32_t* r, uint32_t a) {
    asm volatile("ldmatrix.sync.aligned.m8n8.x4.shared.b16 {%0,%1,%2,%3}, [%4];"
                 : "=r"(r[0]), "=r"(r[1]), "=r"(r[2]), "=r"(r[3]) : "r"(a));
}
__device__ __forceinline__ void mma_bf16(float* d, const uint32_t* a,
                                         uint32_t b0, uint32_t b1) {
    asm volatile(
        "mma.sync.aligned.m16n8k16.row.col.f32.bf16.bf16.f32 "
        "{%0,%1,%2,%3}, {%4,%5,%6,%7}, {%8,%9}, {%0,%1,%2,%3};"
        : "+f"(d[0]), "+f"(d[1]), "+f"(d[2]), "+f"(d[3])
        : "r"(a[0]), "r"(a[1]), "r"(a[2]), "r"(a[3]), "r"(b0), "r"(b1));
}
__device__ __forceinline__ void mma_fp16(float* d, const uint32_t* a,
                                         uint32_t b0, uint32_t b1) {
    asm volatile(
        "mma.sync.aligned.m16n8k16.row.col.f32.f16.f16.f32 "
        "{%0,%1,%2,%3}, {%4,%5,%6,%7}, {%8,%9}, {%0,%1,%2,%3};"
        : "+f"(d[0]), "+f"(d[1]), "+f"(d[2]), "+f"(d[3])
        : "r"(a[0]), "r"(a[1]), "r"(a[2]), "r"(a[3]), "r"(b0), "r"(b1));
}
__device__ __forceinline__ uint32_t packbf(float a, float b) {
    __nv_bfloat162 t = __floats2bfloat162_rn(a, b);
    return *reinterpret_cast<uint32_t*>(&t);
}
__device__ __forceinline__ float bfhi(float v) {
    return __bfloat162float(__float2bfloat16(v));
}

// ---------------- embedding ----------------
__global__ void embed_kernel(const int* __restrict__ inp,
                             const float* __restrict__ wte,
                             const float* __restrict__ wpe,
                             float* __restrict__ x) {
    int i = blockIdx.x * blockDim.x + threadIdx.x;
    if (i >= BT * CC) return;
    int c = i % CC;
    int bt = i / CC;
    int t = bt % TT;
    int tok = inp[bt];
    x[i] = wte[(size_t)tok * CC + c] + wpe[(size_t)t * CC + c];
}

// ---------------- layernorm (warp per row) -> bf16 hi/lo ----------------
__global__ void __launch_bounds__(256)
ln_hl_kernel(const float* __restrict__ in,
             const float* __restrict__ g,
             const float* __restrict__ b,
             __nv_bfloat16* __restrict__ hi,
             __nv_bfloat16* __restrict__ lo) {
    int row = blockIdx.x * 8 + (threadIdx.x >> 5);
    int lane = threadIdx.x & 31;
    const float4* r4 = (const float4*)(in + (size_t)row * CC);

    float4 v[6];
    float s = 0.f;
    #pragma unroll
    for (int i = 0; i < 6; i++) {
        v[i] = r4[lane + i * 32];
        s += v[i].x + v[i].y + v[i].z + v[i].w;
    }
    #pragma unroll
    for (int o = 16; o > 0; o >>= 1) s += __shfl_xor_sync(0xffffffffu, s, o);
    float mu = s / CC;

    float sq = 0.f;
    #pragma unroll
    for (int i = 0; i < 6; i++) {
        float dx = v[i].x - mu, dy = v[i].y - mu, dz = v[i].z - mu, dw = v[i].w - mu;
        sq += dx * dx + dy * dy + dz * dz + dw * dw;
    }
    #pragma unroll
    for (int o = 16; o > 0; o >>= 1) sq += __shfl_xor_sync(0xffffffffu, sq, o);
    float rstd = rsqrtf(sq / CC + 1e-5f);

    const float4* g4 = (const float4*)g;
    const float4* b4 = (const float4*)b;
    uint2* h2 = (uint2*)(hi + (size_t)row * CC);
    uint2* l2 = (uint2*)(lo + (size_t)row * CC);
    #pragma unroll
    for (int i = 0; i < 6; i++) {
        int f4 = lane + i * 32;
        float4 gv = g4[f4], bv = b4[f4];
        float o0 = (v[i].x - mu) * rstd * gv.x + bv.x;
        float o1 = (v[i].y - mu) * rstd * gv.y + bv.y;
        float o2 = (v[i].z - mu) * rstd * gv.z + bv.z;
        float o3 = (v[i].w - mu) * rstd * gv.w + bv.w;
        uint2 hw, lw;
        hw.x = packbf(o0, o1); hw.y = packbf(o2, o3);
        lw.x = packbf(o0 - bfhi(o0), o1 - bfhi(o1));
        lw.y = packbf(o2 - bfhi(o2), o3 - bfhi(o3));
        h2[f4] = hw;
        l2[f4] = lw;
    }
}

// ---------------- final layernorm (warp per row) -> fp16 ----------------
__global__ void __launch_bounds__(256)
ln_hf_kernel(const float* __restrict__ in,
             const float* __restrict__ g,
             const float* __restrict__ b,
             __half* __restrict__ out) {
    int row = blockIdx.x * 8 + (threadIdx.x >> 5);
    int lane = threadIdx.x & 31;
    const float4* r4 = (const float4*)(in + (size_t)row * CC);

    float4 v[6];
    float s = 0.f;
    #pragma unroll
    for (int i = 0; i < 6; i++) {
        v[i] = r4[lane + i * 32];
        s += v[i].x + v[i].y + v[i].z + v[i].w;
    }
    #pragma unroll
    for (int o = 16; o > 0; o >>= 1) s += __shfl_xor_sync(0xffffffffu, s, o);
    float mu = s / CC;

    float sq = 0.f;
    #pragma unroll
    for (int i = 0; i < 6; i++) {
        float dx = v[i].x - mu, dy = v[i].y - mu, dz = v[i].z - mu, dw = v[i].w - mu;
        sq += dx * dx + dy * dy + dz * dz + dw * dw;
    }
    #pragma unroll
    for (int o = 16; o > 0; o >>= 1) sq += __shfl_xor_sync(0xffffffffu, sq, o);
    float rstd = rsqrtf(sq / CC + 1e-5f);

    const float4* g4 = (const float4*)g;
    const float4* b4 = (const float4*)b;
    uint2* o2p = (uint2*)(out + (size_t)row * CC);
    #pragma unroll
    for (int i = 0; i < 6; i++) {
        int f4 = lane + i * 32;
        float4 gv = g4[f4], bv = b4[f4];
        float o0 = (v[i].x - mu) * rstd * gv.x + bv.x;
        float o1 = (v[i].y - mu) * rstd * gv.y + bv.y;
        float o2 = (v[i].z - mu) * rstd * gv.z + bv.z;
        float o3 = (v[i].w - mu) * rstd * gv.w + bv.w;
        __half2 p0 = __floats2half2_rn(o0, o1);
        __half2 p1 = __floats2half2_rn(o2, o3);
        uint2 w;
        w.x = *(uint32_t*)&p0; w.y = *(uint32_t*)&p1;
        o2p[f4] = w;
    }
}

// ---------------- flash attention (bf16x3 mma, online softmax) ----------------
// qkv now bf16 hi/lo — loaders are pure copies / transposes, no conversion math.
#define FA_STRIDE 144
#define FA_TILE   (64 * FA_STRIDE)
#define FA_SMEM   (6 * FA_TILE)

__global__ void __launch_bounds__(128, 3)
fattn_kernel(const __nv_bfloat16* __restrict__ qhi,
             const __nv_bfloat16* __restrict__ qlo,
             __nv_bfloat16* __restrict__ ohi,
             __nv_bfloat16* __restrict__ olo) {
    extern __shared__ char fs[];
    uint32_t sb = smem_u32(fs);
    int qt = 15 - blockIdx.x;
    int bh = blockIdx.y;
    int h = bh % HH, b = bh / HH;
    int tid = threadIdx.x, lane = tid & 31, w = tid >> 5;
    int q0 = qt * 64;
    size_t boff = (size_t)b * TT * C3 + (size_t)h * 3 * HS;
    const __nv_bfloat16* bhp = qhi + boff;
    const __nv_bfloat16* blp = qlo + boff;

    // ---- Q tile load (pure copy) ----
    {
        int r = tid >> 1, c0 = (tid & 1) * 32;
        const uint4* sh = (const uint4*)(bhp + (size_t)(q0 + r) * C3 + c0);
        const uint4* sl = (const uint4*)(blp + (size_t)(q0 + r) * C3 + c0);
        uint4* dh = (uint4*)(fs + 0 * FA_TILE + r * FA_STRIDE + c0 * 2);
        uint4* dl = (uint4*)(fs + 1 * FA_TILE + r * FA_STRIDE + c0 * 2);
        #pragma unroll
        for (int i = 0; i < 4; i++) { dh[i] = sh[i]; dl[i] = sl[i]; }
    }
    __syncthreads();

    int lr = lane & 15, lh = (lane >> 4) * 16;
    uint32_t qh[4][4], ql[4][4];
    #pragma unroll
    for (int kk = 0; kk < 4; kk++) {
        uint32_t ad = sb + 0 * FA_TILE + (uint32_t)(w * 16 + lr) * FA_STRIDE + kk * 32 + lh;
        ldsm4(qh[kk], ad);
        ldsm4(ql[kk], ad + FA_TILE);
    }

    int g = lane >> 2, tg = lane & 3;
    int r0 = q0 + w * 16 + g;
    float m0 = -1e30f, m1 = -1e30f, l0 = 0.f, l1 = 0.f;
    float O[8][4];
    #pragma unroll
    for (int f = 0; f < 8; f++)
        #pragma unroll
        for (int e = 0; e < 4; e++) O[f][e] = 0.f;

    for (int kt = 0; kt <= qt; kt++) {
        __syncthreads();
        // ---- K tile copy + V tile transpose ----
        {
            int r = tid >> 1, c0 = (tid & 1) * 32;
            size_t krow = (size_t)(kt * 64 + r) * C3;
            const uint4* ksh = (const uint4*)(bhp + krow + HS + c0);
            const uint4* ksl = (const uint4*)(blp + krow + HS + c0);
            uint4* kh = (uint4*)(fs + 2 * FA_TILE + r * FA_STRIDE + c0 * 2);
            uint4* kl = (uint4*)(fs + 3 * FA_TILE + r * FA_STRIDE + c0 * 2);
            #pragma unroll
            for (int i = 0; i < 4; i++) { kh[i] = ksh[i]; kl[i] = ksl[i]; }

            const __nv_bfloat16* vsh = bhp + krow + 2 * HS + c0;
            const __nv_bfloat16* vsl = blp + krow + 2 * HS + c0;
            #pragma unroll
            for (int i = 0; i < 32; i++) {
                int d = c0 + i;
                *(__nv_bfloat16*)(fs + 4 * FA_TILE + d * FA_STRIDE + r * 2) = vsh[i];
                *(__nv_bfloat16*)(fs + 5 * FA_TILE + d * FA_STRIDE + r * 2) = vsl[i];
            }
        }
        __syncthreads();

        float S[8][4];
        #pragma unroll
        for (int f = 0; f < 8; f++)
            #pragma unroll
            for (int e = 0; e < 4; e++) S[f][e] = 0.f;

        #pragma unroll
        for (int kk = 0; kk < 4; kk++) {
            #pragma unroll
            for (int nt = 0; nt < 4; nt++) {
                uint32_t bd = sb + 2 * FA_TILE + (uint32_t)(nt * 16 + lr) * FA_STRIDE + kk * 32 + lh;
                uint32_t bhf[4], blf[4];
                ldsm4(bhf, bd);
                ldsm4(blf, bd + FA_TILE);
                #pragma unroll
                for (int sub = 0; sub < 2; sub++) {
                    float* d = S[nt * 2 + sub];
                    mma_bf16(d, qh[kk], bhf[sub], bhf[sub + 2]);
                    mma_bf16(d, qh[kk], blf[sub], blf[sub + 2]);
                    mma_bf16(d, ql[kk], bhf[sub], bhf[sub + 2]);
                }
            }
        }

        #pragma unroll
        for (int f = 0; f < 8; f++)
            #pragma unroll
            for (int e = 0; e < 4; e++) S[f][e] *= SCALE;
        if (kt == qt) {
            #pragma unroll
            for (int f = 0; f < 8; f++) {
                int colb = kt * 64 + f * 8 + tg * 2;
                if (colb     > r0)     S[f][0] = -1e30f;
                if (colb + 1 > r0)     S[f][1] = -1e30f;
                if (colb     > r0 + 8) S[f][2] = -1e30f;
                if (colb + 1 > r0 + 8) S[f][3] = -1e30f;
            }
        }

        float mx0 = -1e30f, mx1 = -1e30f;
        #pragma unroll
        for (int f = 0; f < 8; f++) {
            mx0 = fmaxf(mx0, fmaxf(S[f][0], S[f][1]));
            mx1 = fmaxf(mx1, fmaxf(S[f][2], S[f][3]));
        }
        mx0 = fmaxf(mx0, __shfl_xor_sync(0xffffffffu, mx0, 1));
        mx0 = fmaxf(mx0, __shfl_xor_sync(0xffffffffu, mx0, 2));
        mx1 = fmaxf(mx1, __shfl_xor_sync(0xffffffffu, mx1, 1));
        mx1 = fmaxf(mx1, __shfl_xor_sync(0xffffffffu, mx1, 2));

        float mn0 = fmaxf(m0, mx0), mn1 = fmaxf(m1, mx1);
        float sc0 = __expf(m0 - mn0), sc1 = __expf(m1 - mn1);
        m0 = mn0; m1 = mn1;
        l0 *= sc0; l1 *= sc1;
        #pragma unroll
        for (int f = 0; f < 8; f++) {
            O[f][0] *= sc0; O[f][1] *= sc0;
            O[f][2] *= sc1; O[f][3] *= sc1;
        }

        float ps0 = 0.f, ps1 = 0.f;
        #pragma unroll
        for (int f = 0; f < 8; f++) {
            S[f][0] = __expf(S[f][0] - m0);
            S[f][1] = __expf(S[f][1] - m0);
            S[f][2] = __expf(S[f][2] - m1);
            S[f][3] = __expf(S[f][3] - m1);
            ps0 += S[f][0] + S[f][1];
            ps1 += S[f][2] + S[f][3];
        }
        ps0 += __shfl_xor_sync(0xffffffffu, ps0, 1);
        ps0 += __shfl_xor_sync(0xffffffffu, ps0, 2);
        ps1 += __shfl_xor_sync(0xffffffffu, ps1, 1);
        ps1 += __shfl_xor_sync(0xffffffffu, ps1, 2);
        l0 += ps0; l1 += ps1;

        uint32_t ph[4][4], pl[4][4];
        #pragma unroll
        for (int kk = 0; kk < 4; kk++) {
            float* A0 = S[2 * kk];
            float* A1 = S[2 * kk + 1];
            ph[kk][0] = packbf(A0[0], A0[1]);
            ph[kk][1] = packbf(A0[2], A0[3]);
            ph[kk][2] = packbf(A1[0], A1[1]);
            ph[kk][3] = packbf(A1[2], A1[3]);
            pl[kk][0] = packbf(A0[0] - bfhi(A0[0]), A0[1] - bfhi(A0[1]));
            pl[kk][1] = packbf(A0[2] - bfhi(A0[2]), A0[3] - bfhi(A0[3]));
            pl[kk][2] = packbf(A1[0] - bfhi(A1[0]), A1[1] - bfhi(A1[1]));
            pl[kk][3] = packbf(A1[2] - bfhi(A1[2]), A1[3] - bfhi(A1[3]));
        }

        #pragma unroll
        for (int kk = 0; kk < 4; kk++) {
            #pragma unroll
            for (int nt = 0; nt < 4; nt++) {
                uint32_t bd = sb + 4 * FA_TILE + (uint32_t)(nt * 16 + lr) * FA_STRIDE + kk * 32 + lh;
                uint32_t bhf[4], blf[4];
                ldsm4(bhf, bd);
                ldsm4(blf, bd + FA_TILE);
                #pragma unroll
                for (int sub = 0; sub < 2; sub++) {
                    float* d = O[nt * 2 + sub];
                    mma_bf16(d, ph[kk], bhf[sub], bhf[sub + 2]);
                    mma_bf16(d, ph[kk], blf[sub], blf[sub + 2]);
                    mma_bf16(d, pl[kk], bhf[sub], bhf[sub + 2]);
                }
            }
        }
    }

    float inv0 = 1.f / l0, inv1 = 1.f / l1;
    #pragma unroll
    for (int f = 0; f < 8; f++) {
        int col = h * HS + f * 8 + tg * 2;
        size_t i0 = ((size_t)(b * TT + r0)) * CC + col;
        size_t i1 = i0 + (size_t)8 * CC;
        float v00 = O[f][0] * inv0, v01 = O[f][1] * inv0;
        float v10 = O[f][2] * inv1, v11 = O[f][3] * inv1;
        __nv_bfloat16 h00 = __float2bfloat16(v00);
        __nv_bfloat16 h01 = __float2bfloat16(v01);
        __nv_bfloat16 h10 = __float2bfloat16(v10);
        __nv_bfloat16 h11 = __float2bfloat16(v11);
        ohi[i0]     = h00; olo[i0]     = __float2bfloat16(v00 - __bfloat162float(h00));
        ohi[i0 + 1] = h01; olo[i0 + 1] = __float2bfloat16(v01 - __bfloat162float(h01));
        ohi[i1]     = h10; olo[i1]     = __float2bfloat16(v10 - __bfloat162float(h10));
        ohi[i1 + 1] = h11; olo[i1 + 1] = __float2bfloat16(v11 - __bfloat162float(h11));
    }
}

// ---------------- weight transpose + hi/lo split ----------------
__global__ void conv_wt_kernel(const float* __restrict__ W,
                               __nv_bfloat16* __restrict__ hi,
                               __nv_bfloat16* __restrict__ lo,
                               int K, int N) {
    __shared__ float ts[32][33];
    int k0 = blockIdx.y * 32, n0 = blockIdx.x * 32;
    int tx = threadIdx.x, ty = threadIdx.y;
    #pragma unroll
    for (int i = 0; i < 32; i += 8)
        ts[ty + i][tx] = W[(size_t)(k0 + ty + i) * N + n0 + tx];
    __syncthreads();
    #pragma unroll
    for (int i = 0; i < 32; i += 8) {
        float v = ts[tx][ty + i];
        size_t o = (size_t)(n0 + ty + i) * K + k0 + tx;
        __nv_bfloat16 h = __float2bfloat16(v);
        hi[o] = h;
        lo[o] = __float2bfloat16(v - __bfloat162float(h));
    }
}

// ---------------- wte -> fp16 ----------------
__global__ void conv_hf_kernel(const float* __restrict__ x,
                               __half* __restrict__ out, size_t n) {
    size_t i = (size_t)blockIdx.x * blockDim.x + threadIdx.x;
    if (i < n) out[i] = __float2half(x[i]);
}

// ---------------- HMMA bf16x3 GEMM (R5 config: 8 warps, 32x64 warp tile) ----
#define TSTRIDE  80
#define T_A_HI   0
#define T_A_LO   10240
#define T_B_HI   20480
#define T_B_LO   30720
#define T_STAGE  40960
#define GSMEM    (2 * T_STAGE)

template<bool BIAS, bool GELU, bool RES, bool OUTHL>
__global__ void __launch_bounds__(256, 2)
gemm3_kernel(const __nv_bfloat16* __restrict__ Ahi, const __nv_bfloat16* __restrict__ Alo,
             const __nv_bfloat16* __restrict__ Bhi, const __nv_bfloat16* __restrict__ Blo,
             const float* __restrict__ bias, const float* __restrict__ res,
             float* __restrict__ C,
             __nv_bfloat16* __restrict__ Chi, __nv_bfloat16* __restrict__ Clo,
             int M, int N, int K) {
    extern __shared__ char smem[];
    uint32_t sb = smem_u32(smem);
    int tid = threadIdx.x;
    int lane = tid & 31, wid = tid >> 5;
    int wr = wid >> 1, wc = wid & 1;     // 4x2 warps, warp tile 32x64
    int row0 = blockIdx.y * 128, col0 = blockIdx.x * 128;

    const char* pAhi = (const char*)Ahi;
    const char* pAlo = (const char*)Alo;
    const char* pBhi = (const char*)Bhi;
    const char* pBlo = (const char*)Blo;

    float acc[2][8][4];
    #pragma unroll
    for (int a = 0; a < 2; a++)
        #pragma unroll
        for (int b = 0; b < 8; b++)
            #pragma unroll
            for (int e = 0; e < 4; e++) acc[a][b][e] = 0.f;

    int nc = K / 32;
    size_t Kb = (size_t)K * 2;
    int l_row0 = tid >> 2;
    int l_p    = tid & 3;

    auto load_tile = [&](int c) {
        uint32_t s = sb + (uint32_t)(c & 1) * T_STAGE;
        size_t kb = (size_t)c * 64;
        #pragma unroll
        for (int i = 0; i < 2; i++) {
            int row = l_row0 + i * 64;
            uint32_t so = (uint32_t)row * TSTRIDE + (uint32_t)l_p * 16;
            size_t ao = (size_t)(row0 + row) * Kb + kb + (size_t)l_p * 16;
            cp16(s + T_A_HI + so, pAhi + ao, 16);
            cp16(s + T_A_LO + so, pAlo + ao, 16);
            int nr = col0 + row;
            int v = (nr < N) ? 16 : 0;
            size_t bo = (size_t)((nr < N) ? nr : 0) * Kb + kb + (size_t)l_p * 16;
            cp16(s + T_B_HI + so, pBhi + bo, v);
            cp16(s + T_B_LO + so, pBlo + bo, v);
        }
        cp_commit();
    };

    load_tile(0);

    int lr = lane & 15;
    int lh = (lane >> 4) * 16;

    for (int c = 0; c < nc; c++) {
        if (c + 1 < nc) {
            load_tile(c + 1);
            asm volatile("cp.async.wait_group 1;" ::: "memory");
        } else {
            asm volatile("cp.async.wait_group 0;" ::: "memory");
        }
        __syncthreads();

        uint32_t s = sb + (uint32_t)(c & 1) * T_STAGE;
        #pragma unroll
        for (int ks = 0; ks < 2; ks++) {
            uint32_t ko = ks * 32;
            uint32_t ah[2][4], al[2][4];
            #pragma unroll
            for (int mt = 0; mt < 2; mt++) {
                uint32_t ad = s + T_A_HI +
                              (uint32_t)(wr * 32 + mt * 16 + lr) * TSTRIDE + ko + lh;
                ldsm4(ah[mt], ad);
                ldsm4(al[mt], ad + (T_A_LO - T_A_HI));
            }
            #pragma unroll
            for (int nt = 0; nt < 4; nt++) {
                uint32_t bd = s + T_B_HI +
                              (uint32_t)(wc * 64 + nt * 16 + lr) * TSTRIDE + ko + lh;
                uint32_t bh[4], bl[4];
                ldsm4(bh, bd);
                ldsm4(bl, bd + (T_B_LO - T_B_HI));
                #pragma unroll
                for (int mt = 0; mt < 2; mt++) {
                    #pragma unroll
                    for (int sub = 0; sub < 2; sub++) {
                        float* d = acc[mt][nt * 2 + sub];
                        mma_bf16(d, ah[mt], bh[sub], bh[sub + 2]);
                        mma_bf16(d, ah[mt], bl[sub], bl[sub + 2]);
                        mma_bf16(d, al[mt], bh[sub], bh[sub + 2]);
                    }
                }
            }
        }
        __syncthreads();
    }

    int g = lane >> 2, tg = lane & 3;
    #pragma unroll
    for (int mt = 0; mt < 2; mt++) {
        int r0g = row0 + wr * 32 + mt * 16 + g;
        #pragma unroll
        for (int n8 = 0; n8 < 8; n8++) {
            int gc = col0 + wc * 64 + n8 * 8 + tg * 2;
            float* d = acc[mt][n8];
            #pragma unroll
            for (int e = 0; e < 4; e++) {
                int rr = r0g + ((e >= 2) ? 8 : 0);
                int cc_ = gc + (e & 1);
                if (cc_ < N) {
                    float v = d[e];
                    if (BIAS) v += bias[cc_];
                    if (GELU) v = 0.5f * v * (1.0f + erff(v * 0.7071067811865475f));
                    if (RES)  v += res[(size_t)rr * N + cc_];
                    size_t idx = (size_t)rr * N + cc_;
                    if (OUTHL) {
                        __nv_bfloat16 hv = __float2bfloat16(v);
                        Chi[idx] = hv;
                        Clo[idx] = __float2bfloat16(v - __bfloat162float(hv));
                    } else {
                        C[idx] = v;
                    }
                }
            }
        }
    }
}

// ---------------- HMMA fp16 GEMM (LM head, R5 config) ----------------
#define H_A      0
#define H_B      10240
#define H_STAGE  20480
#define GSMEMH   (2 * H_STAGE)

__global__ void __launch_bounds__(256, 2)
gemmh_kernel(const __half* __restrict__ A, const __half* __restrict__ B,
             float* __restrict__ C, int M, int N, int K) {
    extern __shared__ char smem[];
    uint32_t sb = smem_u32(smem);
    int tid = threadIdx.x;
    int lane = tid & 31, wid = tid >> 5;
    int wr = wid >> 1, wc = wid & 1;
    int row0 = blockIdx.y * 128, col0 = blockIdx.x * 128;

    const char* pA = (const char*)A;
    const char* pB = (const char*)B;

    float acc[2][8][4];
    #pragma unroll
    for (int a = 0; a < 2; a++)
        #pragma unroll
        for (int b = 0; b < 8; b++)
            #pragma unroll
            for (int e = 0; e < 4; e++) acc[a][b][e] = 0.f;

    int nc = K / 32;
    size_t Kb = (size_t)K * 2;
    int l_row0 = tid >> 2;
    int l_p    = tid & 3;

    auto load_tile = [&](int c) {
        uint32_t s = sb + (uint32_t)(c & 1) * H_STAGE;
        size_t kb = (size_t)c * 64;
        #pragma unroll
        for (int i = 0; i < 2; i++) {
            int row = l_row0 + i * 64;
            uint32_t so = (uint32_t)row * TSTRIDE + (uint32_t)l_p * 16;
            size_t ao = (size_t)(row0 + row) * Kb + kb + (size_t)l_p * 16;
            cp16(s + H_A + so, pA + ao, 16);
            int nr = col0 + row;
            int v = (nr < N) ? 16 : 0;
            size_t bo = (size_t)((nr < N) ? nr : 0) * Kb + kb + (size_t)l_p * 16;
            cp16(s + H_B + so, pB + bo, v);
        }
        cp_commit();
    };

    load_tile(0);

    int lr = lane & 15;
    int lh = (lane >> 4) * 16;

    for (int c = 0; c < nc; c++) {
        if (c + 1 < nc) {
            load_tile(c + 1);
            asm volatile("cp.async.wait_group 1;" ::: "memory");
        } else {
            asm volatile("cp.async.wait_group 0;" ::: "memory");
        }
        __syncthreads();

        uint32_t s = sb + (uint32_t)(c & 1) * H_STAGE;
        #pragma unroll
        for (int ks = 0; ks < 2; ks++) {
            uint32_t ko = ks * 32;
            uint32_t ah[2][4];
            #pragma unroll
            for (int mt = 0; mt < 2; mt++) {
                uint32_t ad = s + H_A +
                              (uint32_t)(wr * 32 + mt * 16 + lr) * TSTRIDE + ko + lh;
                ldsm4(ah[mt], ad);
            }
            #pragma unroll
            for (int nt = 0; nt < 4; nt++) {
                uint32_t bd = s + H_B +
                              (uint32_t)(wc * 64 + nt * 16 + lr) * TSTRIDE + ko + lh;
                uint32_t bf[4];
                ldsm4(bf, bd);
                #pragma unroll
                for (int mt = 0; mt < 2; mt++) {
                    #pragma unroll
                    for (int sub = 0; sub < 2; sub++)
                        mma_fp16(acc[mt][nt * 2 + sub], ah[mt], bf[sub], bf[sub + 2]);
                }
            }
        }
        __syncthreads();
    }

    int g = lane >> 2, tg = lane & 3;
    #pragma unroll
    for (int mt = 0; mt < 2; mt++) {
        int r0g = row0 + wr * 32 + mt * 16 + g;
        #pragma unroll
        for (int n8 = 0; n8 < 8; n8++) {
            int gc = col0 + wc * 64 + n8 * 8 + tg * 2;
            float* d = acc[mt][n8];
            #pragma unroll
            for (int e = 0; e < 4; e++) {
                int rr = r0g + ((e >= 2) ? 8 : 0);
                int cc_ = gc + (e & 1);
                if (cc_ < N) C[(size_t)rr * N + cc_] = d[e];
            }
        }
    }
}

// ---------------- host orchestration ----------------
static void conv_wT(const float* W, __nv_bfloat16* hi, __nv_bfloat16* lo, int K, int N) {
    conv_wt_kernel<<<dim3(N / 32, K / 32), dim3(32, 8)>>>(W, hi, lo, K, N);
}

template<bool BIAS, bool GELU, bool RES, bool OUTHL>
static void gemm3(const __nv_bfloat16* ahi, const __nv_bfloat16* alo,
                  const __nv_bfloat16* bhi, const __nv_bfloat16* blo,
                  const float* bias, const float* res,
                  float* C, __nv_bfloat16* Chi, __nv_bfloat16* Clo,
                  int M, int N, int K) {
    dim3 grid((N + 127) / 128, M / 128);
    gemm3_kernel<BIAS, GELU, RES, OUTHL><<<grid, 256, GSMEM>>>(
        ahi, alo, bhi, blo, bias, res, C, Chi, Clo, M, N, K);
}

extern "C" void kernel_launch(void* const* d_in, const int* in_sizes, int n_in,
                              void* d_out, int out_size) {
    const int*   inp   = (const int*)  d_in[0];
    const float* wte   = (const float*)d_in[1];
    const float* wpe   = (const float*)d_in[2];
    const float* ln1_g = (const float*)d_in[3];
    const float* ln1_b = (const float*)d_in[4];
    const float* wqkv  = (const float*)d_in[5];
    const float* bqkv  = (const float*)d_in[6];
    const float* wout  = (const float*)d_in[7];
    const float* bout  = (const float*)d_in[8];
    const float* ln2_g = (const float*)d_in[9];
    const float* ln2_b = (const float*)d_in[10];
    const float* wfc1  = (const float*)d_in[11];
    const float* bfc1  = (const float*)d_in[12];
    const float* wfc2  = (const float*)d_in[13];
    const float* bfc2  = (const float*)d_in[14];
    const float* lnf_g = (const float*)d_in[15];
    const float* lnf_b = (const float*)d_in[16];
    float* logits = (float*)d_out;

    float *x;
    __nv_bfloat16 *qhi, *qlo, *ahi, *alo, *fhi, *flo, *whi, *wlo;
    __half *ahf, *tef;
    cudaGetSymbolAddress((void**)&x,   g_x);
    cudaGetSymbolAddress((void**)&qhi, g_qhi);
    cudaGetSymbolAddress((void**)&qlo, g_qlo);
    cudaGetSymbolAddress((void**)&ahi, g_ahi);
    cudaGetSymbolAddress((void**)&alo, g_alo);
    cudaGetSymbolAddress((void**)&fhi, g_fhi);
    cudaGetSymbolAddress((void**)&flo, g_flo);
    cudaGetSymbolAddress((void**)&whi, g_whi);
    cudaGetSymbolAddress((void**)&wlo, g_wlo);
    cudaGetSymbolAddress((void**)&ahf, g_ahf);
    cudaGetSymbolAddress((void**)&tef, g_tef);

    cudaFuncSetAttribute(gemm3_kernel<true,  false, false, true >, cudaFuncAttributeMaxDynamicSharedMemorySize, GSMEM);
    cudaFuncSetAttribute(gemm3_kernel<true,  false, true,  false>, cudaFuncAttributeMaxDynamicSharedMemorySize, GSMEM);
    cudaFuncSetAttribute(gemm3_kernel<true,  true,  false, true >, cudaFuncAttributeMaxDynamicSharedMemorySize, GSMEM);
    cudaFuncSetAttribute(gemmh_kernel, cudaFuncAttributeMaxDynamicSharedMemorySize, GSMEMH);
    cudaFuncSetAttribute(fattn_kernel, cudaFuncAttributeMaxDynamicSharedMemorySize, FA_SMEM);

    embed_kernel<<<(BT * CC + 255) / 256, 256>>>(inp, wte, wpe, x);

    for (int l = 0; l < NL; l++) {
        const float* g1  = ln1_g + (size_t)l * CC;
        const float* b1  = ln1_b + (size_t)l * CC;
        const float* wq  = wqkv  + (size_t)l * CC * C3;
        const float* bq  = bqkv  + (size_t)l * C3;
        const float* wo  = wout  + (size_t)l * CC * CC;
        const float* bo  = bout  + (size_t)l * CC;
        const float* g2  = ln2_g + (size_t)l * CC;
        const float* b2  = ln2_b + (size_t)l * CC;
        const float* w1  = wfc1  + (size_t)l * CC * C4;
        const float* bb1 = bfc1  + (size_t)l * C4;
        const float* w2  = wfc2  + (size_t)l * C4 * CC;
        const float* bb2 = bfc2  + (size_t)l * CC;

        // ln1 -> hi/lo ; qkv = h @ wq + bq  -> bf16 hi/lo directly
        ln_hl_kernel<<<BT / 8, 256>>>(x, g1, b1, ahi, alo);
        conv_wT(wq, whi, wlo, CC, C3);
        gemm3<true, false, false, true>(ahi, alo, whi, wlo, bq, nullptr,
                                        nullptr, qhi, qlo, BT, C3, CC);

        // flash attention on bf16 hi/lo qkv
        fattn_kernel<<<dim3(16, BB * HH), 128, FA_SMEM>>>(qhi, qlo, ahi, alo);

        // x = x + atty @ wo + bo
        conv_wT(wo, whi, wlo, CC, CC);
        gemm3<true, false, true, false>(ahi, alo, whi, wlo, bo, x,
                                        x, nullptr, nullptr, BT, CC, CC);

        // ln2 -> hi/lo ; fc1 = gelu(h @ w1 + bb1) -> hi/lo directly
        ln_hl_kernel<<<BT / 8, 256>>>(x, g2, b2, ahi, alo);
        conv_wT(w1, whi, wlo, CC, C4);
        gemm3<true, true, false, true>(ahi, alo, whi, wlo, bb1, nullptr,
                                       nullptr, fhi, flo, BT, C4, CC);

        // x = x + fc1 @ w2 + bb2
        conv_wT(w2, whi, wlo, C4, CC);
        gemm3<true, false, true, false>(fhi, flo, whi, wlo, bb2, x,
                                        x, nullptr, nullptr, BT, CC, C4);
    }

    ln_hf_kernel<<<BT / 8, 256>>>(x, lnf_g, lnf_b, ahf);
    conv_hf_kernel<<<(unsigned)(((size_t)VV * CC + 255) / 256), 256>>>(
        wte, tef, (size_t)VV * CC);
    {
        dim3 grid((VV + 127) / 128, BT / 128);
        gemmh_kernel<<<grid, 256, GSMEMH>>>(ahf, tef, logits, BT, VV, CC);
    }
}

// round 8
// speedup vs baseline: 1.6078x; 1.0324x over previous
#include <cuda_runtime.h>
#include <cuda_bf16.h>
#include <cuda_fp16.h>
#include <math.h>
#include <stdint.h>

// ---------------- problem constants ----------------
#define NL   12
#define BB   4
#define TT   1024
#define CC   768
#define HH   12
#define HS   64
#define VV   50257
#define BT   (BB * TT)
#define C3   (3 * CC)
#define C4   (4 * CC)
#define SCALE 0.125f

// ---------------- device scratch ----------------
__device__ float g_x[BT * CC];
__device__ __nv_bfloat16 g_qhi[BT * C3];
__device__ __nv_bfloat16 g_qlo[BT * C3];
__device__ __nv_bfloat16 g_ahi[BT * CC];
__device__ __nv_bfloat16 g_alo[BT * CC];
__device__ __nv_bfloat16 g_fhi[BT * C4];
__device__ __nv_bfloat16 g_flo[BT * C4];
__device__ __nv_bfloat16 g_whi[C4 * CC];
__device__ __nv_bfloat16 g_wlo[C4 * CC];
__device__ __half g_ahf[BT * CC];
__device__ __half g_tef[(size_t)VV * CC];

// ---------------- PTX helpers ----------------
__device__ __forceinline__ uint32_t smem_u32(const void* p) {
    uint32_t a;
    asm("{ .reg .u64 t; cvta.to.shared.u64 t, %1; cvt.u32.u64 %0, t; }" : "=r"(a) : "l"(p));
    return a;
}
__device__ __forceinline__ void cp16(uint32_t dst, const void* src, int sz) {
    asm volatile("cp.async.ca.shared.global [%0], [%1], 16, %2;"
                 :: "r"(dst), "l"(src), "r"(sz) : "memory");
}
__device__ __forceinline__ void cp_commit() {
    asm volatile("cp.async.commit_group;" ::: "memory");
}
__device__ __forceinline__ void ldsm4(uint32_t* r, uint32_t a) {
    asm volatile("ldmatrix.sync.aligned.m8n8.x4.shared.b16 {%0,%1,%2,%3}, [%4];"
                 : "=r"(r[0]), "=r"(r[1]), "=r"(r[2]), "=r"(r[3]) : "r"(a));
}
__device__ __forceinline__ void ldsm4t(uint32_t* r, uint32_t a) {
    asm volatile("ldmatrix.sync.aligned.m8n8.x4.trans.shared.b16 {%0,%1,%2,%3}, [%4];"
                 : "=r"(r[0]), "=r"(r[1]), "=r"(r[2]), "=r"(r[3]) : "r"(a));
}
__device__ __forceinline__ void mma_bf16(float* d, const uint32_t* a,
                                         uint32_t b0, uint32_t b1) {
    asm volatile(
        "mma.sync.aligned.m16n8k16.row.col.f32.bf16.bf16.f32 "
        "{%0,%1,%2,%3}, {%4,%5,%6,%7}, {%8,%9}, {%0,%1,%2,%3};"
        : "+f"(d[0]), "+f"(d[1]), "+f"(d[2]), "+f"(d[3])
        : "r"(a[0]), "r"(a[1]), "r"(a[2]), "r"(a[3]), "r"(b0), "r"(b1));
}
__device__ __forceinline__ void mma_fp16(float* d, const uint32_t* a,
                                         uint32_t b0, uint32_t b1) {
    asm volatile(
        "mma.sync.aligned.m16n8k16.row.col.f32.f16.f16.f32 "
        "{%0,%1,%2,%3}, {%4,%5,%6,%7}, {%8,%9}, {%0,%1,%2,%3};"
        : "+f"(d[0]), "+f"(d[1]), "+f"(d[2]), "+f"(d[3])
        : "r"(a[0]), "r"(a[1]), "r"(a[2]), "r"(a[3]), "r"(b0), "r"(b1));
}
__device__ __forceinline__ uint32_t packbf(float a, float b) {
    __nv_bfloat162 t = __floats2bfloat162_rn(a, b);
    return *reinterpret_cast<uint32_t*>(&t);
}
__device__ __forceinline__ float bfhi(float v) {
    return __bfloat162float(__float2bfloat16(v));
}

// ---------------- embedding ----------------
__global__ void embed_kernel(const int* __restrict__ inp,
                             const float* __restrict__ wte,
                             const float* __restrict__ wpe,
                             float* __restrict__ x) {
    int i = blockIdx.x * blockDim.x + threadIdx.x;
    if (i >= BT * CC) return;
    int c = i % CC;
    int bt = i / CC;
    int t = bt % TT;
    int tok = inp[bt];
    x[i] = wte[(size_t)tok * CC + c] + wpe[(size_t)t * CC + c];
}

// ---------------- layernorm (warp per row) -> bf16 hi/lo ----------------
__global__ void __launch_bounds__(256)
ln_hl_kernel(const float* __restrict__ in,
             const float* __restrict__ g,
             const float* __restrict__ b,
             __nv_bfloat16* __restrict__ hi,
             __nv_bfloat16* __restrict__ lo) {
    int row = blockIdx.x * 8 + (threadIdx.x >> 5);
    int lane = threadIdx.x & 31;
    const float4* r4 = (const float4*)(in + (size_t)row * CC);

    float4 v[6];
    float s = 0.f;
    #pragma unroll
    for (int i = 0; i < 6; i++) {
        v[i] = r4[lane + i * 32];
        s += v[i].x + v[i].y + v[i].z + v[i].w;
    }
    #pragma unroll
    for (int o = 16; o > 0; o >>= 1) s += __shfl_xor_sync(0xffffffffu, s, o);
    float mu = s / CC;

    float sq = 0.f;
    #pragma unroll
    for (int i = 0; i < 6; i++) {
        float dx = v[i].x - mu, dy = v[i].y - mu, dz = v[i].z - mu, dw = v[i].w - mu;
        sq += dx * dx + dy * dy + dz * dz + dw * dw;
    }
    #pragma unroll
    for (int o = 16; o > 0; o >>= 1) sq += __shfl_xor_sync(0xffffffffu, sq, o);
    float rstd = rsqrtf(sq / CC + 1e-5f);

    const float4* g4 = (const float4*)g;
    const float4* b4 = (const float4*)b;
    uint2* h2 = (uint2*)(hi + (size_t)row * CC);
    uint2* l2 = (uint2*)(lo + (size_t)row * CC);
    #pragma unroll
    for (int i = 0; i < 6; i++) {
        int f4 = lane + i * 32;
        float4 gv = g4[f4], bv = b4[f4];
        float o0 = (v[i].x - mu) * rstd * gv.x + bv.x;
        float o1 = (v[i].y - mu) * rstd * gv.y + bv.y;
        float o2 = (v[i].z - mu) * rstd * gv.z + bv.z;
        float o3 = (v[i].w - mu) * rstd * gv.w + bv.w;
        uint2 hw, lw;
        hw.x = packbf(o0, o1); hw.y = packbf(o2, o3);
        lw.x = packbf(o0 - bfhi(o0), o1 - bfhi(o1));
        lw.y = packbf(o2 - bfhi(o2), o3 - bfhi(o3));
        h2[f4] = hw;
        l2[f4] = lw;
    }
}

// ---------------- final layernorm (warp per row) -> fp16 ----------------
__global__ void __launch_bounds__(256)
ln_hf_kernel(const float* __restrict__ in,
             const float* __restrict__ g,
             const float* __restrict__ b,
             __half* __restrict__ out) {
    int row = blockIdx.x * 8 + (threadIdx.x >> 5);
    int lane = threadIdx.x & 31;
    const float4* r4 = (const float4*)(in + (size_t)row * CC);

    float4 v[6];
    float s = 0.f;
    #pragma unroll
    for (int i = 0; i < 6; i++) {
        v[i] = r4[lane + i * 32];
        s += v[i].x + v[i].y + v[i].z + v[i].w;
    }
    #pragma unroll
    for (int o = 16; o > 0; o >>= 1) s += __shfl_xor_sync(0xffffffffu, s, o);
    float mu = s / CC;

    float sq = 0.f;
    #pragma unroll
    for (int i = 0; i < 6; i++) {
        float dx = v[i].x - mu, dy = v[i].y - mu, dz = v[i].z - mu, dw = v[i].w - mu;
        sq += dx * dx + dy * dy + dz * dz + dw * dw;
    }
    #pragma unroll
    for (int o = 16; o > 0; o >>= 1) sq += __shfl_xor_sync(0xffffffffu, sq, o);
    float rstd = rsqrtf(sq / CC + 1e-5f);

    const float4* g4 = (const float4*)g;
    const float4* b4 = (const float4*)b;
    uint2* o2p = (uint2*)(out + (size_t)row * CC);
    #pragma unroll
    for (int i = 0; i < 6; i++) {
        int f4 = lane + i * 32;
        float4 gv = g4[f4], bv = b4[f4];
        float o0 = (v[i].x - mu) * rstd * gv.x + bv.x;
        float o1 = (v[i].y - mu) * rstd * gv.y + bv.y;
        float o2 = (v[i].z - mu) * rstd * gv.z + bv.z;
        float o3 = (v[i].w - mu) * rstd * gv.w + bv.w;
        __half2 p0 = __floats2half2_rn(o0, o1);
        __half2 p1 = __floats2half2_rn(o2, o3);
        uint2 w;
        w.x = *(uint32_t*)&p0; w.y = *(uint32_t*)&p1;
        o2p[f4] = w;
    }
}

// ---------------- flash attention v2 ----------------
// cp.async double-buffered K/V stages; V row-major + ldmatrix.trans;
// PV uses Phi*(Vhi+Vlo) (P-lo term dropped).
#define FA_STRIDE 144
#define FA_TILE   (64 * FA_STRIDE)          // 9216 B
#define FA_KV0    (2 * FA_TILE)             // after Qhi,Qlo
#define FA_STAGE  (4 * FA_TILE)             // Khi,Klo,Vhi,Vlo
#define FA_SMEM   (2 * FA_TILE + 2 * FA_STAGE)   // 92160 B

__global__ void __launch_bounds__(128, 2)
fattn_kernel(const __nv_bfloat16* __restrict__ qhi,
             const __nv_bfloat16* __restrict__ qlo,
             __nv_bfloat16* __restrict__ ohi,
             __nv_bfloat16* __restrict__ olo) {
    extern __shared__ char fs[];
    uint32_t sb = smem_u32(fs);
    int qt = 15 - blockIdx.x;
    int bh = blockIdx.y;
    int h = bh % HH, b = bh / HH;
    int tid = threadIdx.x, lane = tid & 31, w = tid >> 5;
    int q0 = qt * 64;
    size_t boff = (size_t)b * TT * C3 + (size_t)h * 3 * HS;
    const __nv_bfloat16* bhp = qhi + boff;
    const __nv_bfloat16* blp = qlo + boff;

    int lrow = tid >> 1, lc = (tid & 1) * 32;   // loader coords
    uint32_t lso = (uint32_t)lrow * FA_STRIDE + (uint32_t)lc * 2;

    // ---- issue KV stage load for tile kt into stage s (cp.async) ----
    auto load_kv = [&](int kt, int s) {
        uint32_t base = sb + FA_KV0 + (uint32_t)s * FA_STAGE;
        size_t krow = (size_t)(kt * 64 + lrow) * C3 + lc;
        const char* kh = (const char*)(bhp + krow + HS);
        const char* kl = (const char*)(blp + krow + HS);
        const char* vh = (const char*)(bhp + krow + 2 * HS);
        const char* vl = (const char*)(blp + krow + 2 * HS);
        #pragma unroll
        for (int i = 0; i < 4; i++) {
            cp16(base + 0 * FA_TILE + lso + i * 16, kh + i * 16, 16);
            cp16(base + 1 * FA_TILE + lso + i * 16, kl + i * 16, 16);
            cp16(base + 2 * FA_TILE + lso + i * 16, vh + i * 16, 16);
            cp16(base + 3 * FA_TILE + lso + i * 16, vl + i * 16, 16);
        }
        cp_commit();
    };

    // ---- Q tile load (plain copy, once) ----
    {
        const uint4* sh = (const uint4*)(bhp + (size_t)(q0 + lrow) * C3 + lc);
        const uint4* sl = (const uint4*)(blp + (size_t)(q0 + lrow) * C3 + lc);
        uint4* dh = (uint4*)(fs + 0 * FA_TILE + lrow * FA_STRIDE + lc * 2);
        uint4* dl = (uint4*)(fs + 1 * FA_TILE + lrow * FA_STRIDE + lc * 2);
        #pragma unroll
        for (int i = 0; i < 4; i++) { dh[i] = sh[i]; dl[i] = sl[i]; }
    }
    load_kv(0, 0);
    __syncthreads();

    int lr = lane & 15, lh = (lane >> 4) * 16;
    uint32_t qh[4][4], ql[4][4];
    #pragma unroll
    for (int kk = 0; kk < 4; kk++) {
        uint32_t ad = sb + 0 * FA_TILE + (uint32_t)(w * 16 + lr) * FA_STRIDE + kk * 32 + lh;
        ldsm4(qh[kk], ad);
        ldsm4(ql[kk], ad + FA_TILE);
    }

    // trans-ldsm lane address components for V (row = k, col = n)
    uint32_t vrow_l = (uint32_t)((lane & 7) + ((lane >> 4) << 3));   // k within 16
    uint32_t vcol_l = (uint32_t)(((lane >> 3) & 1) * 16);            // bytes (n-half)

    int g = lane >> 2, tg = lane & 3;
    int r0 = q0 + w * 16 + g;
    float m0 = -1e30f, m1 = -1e30f, l0 = 0.f, l1 = 0.f;
    float O[8][4];
    #pragma unroll
    for (int f = 0; f < 8; f++)
        #pragma unroll
        for (int e = 0; e < 4; e++) O[f][e] = 0.f;

    for (int kt = 0; kt <= qt; kt++) {
        int buf = kt & 1;
        if (kt + 1 <= qt) {
            load_kv(kt + 1, buf ^ 1);
            asm volatile("cp.async.wait_group 1;" ::: "memory");
        } else {
            asm volatile("cp.async.wait_group 0;" ::: "memory");
        }
        __syncthreads();

        uint32_t stage = sb + FA_KV0 + (uint32_t)buf * FA_STAGE;

        // ---- S = Q K^T (bf16x3) ----
        float S[8][4];
        #pragma unroll
        for (int f = 0; f < 8; f++)
            #pragma unroll
            for (int e = 0; e < 4; e++) S[f][e] = 0.f;

        #pragma unroll
        for (int kk = 0; kk < 4; kk++) {
            #pragma unroll
            for (int nt = 0; nt < 4; nt++) {
                uint32_t bd = stage + (uint32_t)(nt * 16 + lr) * FA_STRIDE + kk * 32 + lh;
                uint32_t bhf[4], blf[4];
                ldsm4(bhf, bd);
                ldsm4(blf, bd + FA_TILE);
                #pragma unroll
                for (int sub = 0; sub < 2; sub++) {
                    float* d = S[nt * 2 + sub];
                    mma_bf16(d, qh[kk], bhf[sub], bhf[sub + 2]);
                    mma_bf16(d, qh[kk], blf[sub], blf[sub + 2]);
                    mma_bf16(d, ql[kk], bhf[sub], bhf[sub + 2]);
                }
            }
        }

        #pragma unroll
        for (int f = 0; f < 8; f++)
            #pragma unroll
            for (int e = 0; e < 4; e++) S[f][e] *= SCALE;
        if (kt == qt) {
            #pragma unroll
            for (int f = 0; f < 8; f++) {
                int colb = kt * 64 + f * 8 + tg * 2;
                if (colb     > r0)     S[f][0] = -1e30f;
                if (colb + 1 > r0)     S[f][1] = -1e30f;
                if (colb     > r0 + 8) S[f][2] = -1e30f;
                if (colb + 1 > r0 + 8) S[f][3] = -1e30f;
            }
        }

        // ---- online softmax ----
        float mx0 = -1e30f, mx1 = -1e30f;
        #pragma unroll
        for (int f = 0; f < 8; f++) {
            mx0 = fmaxf(mx0, fmaxf(S[f][0], S[f][1]));
            mx1 = fmaxf(mx1, fmaxf(S[f][2], S[f][3]));
        }
        mx0 = fmaxf(mx0, __shfl_xor_sync(0xffffffffu, mx0, 1));
        mx0 = fmaxf(mx0, __shfl_xor_sync(0xffffffffu, mx0, 2));
        mx1 = fmaxf(mx1, __shfl_xor_sync(0xffffffffu, mx1, 1));
        mx1 = fmaxf(mx1, __shfl_xor_sync(0xffffffffu, mx1, 2));

        float mn0 = fmaxf(m0, mx0), mn1 = fmaxf(m1, mx1);
        float sc0 = __expf(m0 - mn0), sc1 = __expf(m1 - mn1);
        m0 = mn0; m1 = mn1;
        l0 *= sc0; l1 *= sc1;
        #pragma unroll
        for (int f = 0; f < 8; f++) {
            O[f][0] *= sc0; O[f][1] *= sc0;
            O[f][2] *= sc1; O[f][3] *= sc1;
        }

        float ps0 = 0.f, ps1 = 0.f;
        #pragma unroll
        for (int f = 0; f < 8; f++) {
            S[f][0] = __expf(S[f][0] - m0);
            S[f][1] = __expf(S[f][1] - m0);
            S[f][2] = __expf(S[f][2] - m1);
            S[f][3] = __expf(S[f][3] - m1);
            ps0 += S[f][0] + S[f][1];
            ps1 += S[f][2] + S[f][3];
        }
        ps0 += __shfl_xor_sync(0xffffffffu, ps0, 1);
        ps0 += __shfl_xor_sync(0xffffffffu, ps0, 2);
        ps1 += __shfl_xor_sync(0xffffffffu, ps1, 1);
        ps1 += __shfl_xor_sync(0xffffffffu, ps1, 2);
        l0 += ps0; l1 += ps1;

        // ---- P fragments (hi only) ----
        uint32_t ph[4][4];
        #pragma unroll
        for (int kk = 0; kk < 4; kk++) {
            float* A0 = S[2 * kk];
            float* A1 = S[2 * kk + 1];
            ph[kk][0] = packbf(A0[0], A0[1]);
            ph[kk][1] = packbf(A0[2], A0[3]);
            ph[kk][2] = packbf(A1[0], A1[1]);
            ph[kk][3] = packbf(A1[2], A1[3]);
        }

        // ---- O += P (Vhi + Vlo), V row-major via ldmatrix.trans ----
        #pragma unroll
        for (int kk = 0; kk < 4; kk++) {
            uint32_t vr = (uint32_t)(kk * 16) + vrow_l;
            #pragma unroll
            for (int nt = 0; nt < 4; nt++) {
                uint32_t bd = stage + 2 * FA_TILE + vr * FA_STRIDE + (uint32_t)(nt * 32) + vcol_l;
                uint32_t bhf[4], blf[4];
                ldsm4t(bhf, bd);
                ldsm4t(blf, bd + FA_TILE);
                #pragma unroll
                for (int sub = 0; sub < 2; sub++) {
                    float* d = O[nt * 2 + sub];
                    mma_bf16(d, ph[kk], bhf[sub], bhf[sub + 2]);
                    mma_bf16(d, ph[kk], blf[sub], blf[sub + 2]);
                }
            }
        }
        __syncthreads();   // all reads of `buf` done before it is reloaded
    }

    float inv0 = 1.f / l0, inv1 = 1.f / l1;
    #pragma unroll
    for (int f = 0; f < 8; f++) {
        int col = h * HS + f * 8 + tg * 2;
        size_t i0 = ((size_t)(b * TT + r0)) * CC + col;
        size_t i1 = i0 + (size_t)8 * CC;
        float v00 = O[f][0] * inv0, v01 = O[f][1] * inv0;
        float v10 = O[f][2] * inv1, v11 = O[f][3] * inv1;
        __nv_bfloat16 h00 = __float2bfloat16(v00);
        __nv_bfloat16 h01 = __float2bfloat16(v01);
        __nv_bfloat16 h10 = __float2bfloat16(v10);
        __nv_bfloat16 h11 = __float2bfloat16(v11);
        ohi[i0]     = h00; olo[i0]     = __float2bfloat16(v00 - __bfloat162float(h00));
        ohi[i0 + 1] = h01; olo[i0 + 1] = __float2bfloat16(v01 - __bfloat162float(h01));
        ohi[i1]     = h10; olo[i1]     = __float2bfloat16(v10 - __bfloat162float(h10));
        ohi[i1 + 1] = h11; olo[i1 + 1] = __float2bfloat16(v11 - __bfloat162float(h11));
    }
}

// ---------------- weight transpose + hi/lo split ----------------
__global__ void conv_wt_kernel(const float* __restrict__ W,
                               __nv_bfloat16* __restrict__ hi,
                               __nv_bfloat16* __restrict__ lo,
                               int K, int N) {
    __shared__ float ts[32][33];
    int k0 = blockIdx.y * 32, n0 = blockIdx.x * 32;
    int tx = threadIdx.x, ty = threadIdx.y;
    #pragma unroll
    for (int i = 0; i < 32; i += 8)
        ts[ty + i][tx] = W[(size_t)(k0 + ty + i) * N + n0 + tx];
    __syncthreads();
    #pragma unroll
    for (int i = 0; i < 32; i += 8) {
        float v = ts[tx][ty + i];
        size_t o = (size_t)(n0 + ty + i) * K + k0 + tx;
        __nv_bfloat16 h = __float2bfloat16(v);
        hi[o] = h;
        lo[o] = __float2bfloat16(v - __bfloat162float(h));
    }
}

// ---------------- wte -> fp16 ----------------
__global__ void conv_hf_kernel(const float* __restrict__ x,
                               __half* __restrict__ out, size_t n) {
    size_t i = (size_t)blockIdx.x * blockDim.x + threadIdx.x;
    if (i < n) out[i] = __float2half(x[i]);
}

// ---------------- HMMA bf16x3 GEMM (8 warps, 32x64 warp tile) ----------------
#define TSTRIDE  80
#define T_A_HI   0
#define T_A_LO   10240
#define T_B_HI   20480
#define T_B_LO   30720
#define T_STAGE  40960
#define GSMEM    (2 * T_STAGE)

template<bool BIAS, bool GELU, bool RES, bool OUTHL>
__global__ void __launch_bounds__(256, 2)
gemm3_kernel(const __nv_bfloat16* __restrict__ Ahi, const __nv_bfloat16* __restrict__ Alo,
             const __nv_bfloat16* __restrict__ Bhi, const __nv_bfloat16* __restrict__ Blo,
             const float* __restrict__ bias, const float* __restrict__ res,
             float* __restrict__ C,
             __nv_bfloat16* __restrict__ Chi, __nv_bfloat16* __restrict__ Clo,
             int M, int N, int K) {
    extern __shared__ char smem[];
    uint32_t sb = smem_u32(smem);
    int tid = threadIdx.x;
    int lane = tid & 31, wid = tid >> 5;
    int wr = wid >> 1, wc = wid & 1;
    int row0 = blockIdx.y * 128, col0 = blockIdx.x * 128;

    const char* pAhi = (const char*)Ahi;
    const char* pAlo = (const char*)Alo;
    const char* pBhi = (const char*)Bhi;
    const char* pBlo = (const char*)Blo;

    float acc[2][8][4];
    #pragma unroll
    for (int a = 0; a < 2; a++)
        #pragma unroll
        for (int b = 0; b < 8; b++)
            #pragma unroll
            for (int e = 0; e < 4; e++) acc[a][b][e] = 0.f;

    int nc = K / 32;
    size_t Kb = (size_t)K * 2;
    int l_row0 = tid >> 2;
    int l_p    = tid & 3;

    auto load_tile = [&](int c) {
        uint32_t s = sb + (uint32_t)(c & 1) * T_STAGE;
        size_t kb = (size_t)c * 64;
        #pragma unroll
        for (int i = 0; i < 2; i++) {
            int row = l_row0 + i * 64;
            uint32_t so = (uint32_t)row * TSTRIDE + (uint32_t)l_p * 16;
            size_t ao = (size_t)(row0 + row) * Kb + kb + (size_t)l_p * 16;
            cp16(s + T_A_HI + so, pAhi + ao, 16);
            cp16(s + T_A_LO + so, pAlo + ao, 16);
            int nr = col0 + row;
            int v = (nr < N) ? 16 : 0;
            size_t bo = (size_t)((nr < N) ? nr : 0) * Kb + kb + (size_t)l_p * 16;
            cp16(s + T_B_HI + so, pBhi + bo, v);
            cp16(s + T_B_LO + so, pBlo + bo, v);
        }
        cp_commit();
    };

    load_tile(0);

    int lr = lane & 15;
    int lh = (lane >> 4) * 16;

    for (int c = 0; c < nc; c++) {
        if (c + 1 < nc) {
            load_tile(c + 1);
            asm volatile("cp.async.wait_group 1;" ::: "memory");
        } else {
            asm volatile("cp.async.wait_group 0;" ::: "memory");
        }
        __syncthreads();

        uint32_t s = sb + (uint32_t)(c & 1) * T_STAGE;
        #pragma unroll
        for (int ks = 0; ks < 2; ks++) {
            uint32_t ko = ks * 32;
            uint32_t ah[2][4], al[2][4];
            #pragma unroll
            for (int mt = 0; mt < 2; mt++) {
                uint32_t ad = s + T_A_HI +
                              (uint32_t)(wr * 32 + mt * 16 + lr) * TSTRIDE + ko + lh;
                ldsm4(ah[mt], ad);
                ldsm4(al[mt], ad + (T_A_LO - T_A_HI));
            }
            #pragma unroll
            for (int nt = 0; nt < 4; nt++) {
                uint32_t bd = s + T_B_HI +
                              (uint32_t)(wc * 64 + nt * 16 + lr) * TSTRIDE + ko + lh;
                uint32_t bh[4], bl[4];
                ldsm4(bh, bd);
                ldsm4(bl, bd + (T_B_LO - T_B_HI));
                #pragma unroll
                for (int mt = 0; mt < 2; mt++) {
                    #pragma unroll
                    for (int sub = 0; sub < 2; sub++) {
                        float* d = acc[mt][nt * 2 + sub];
                        mma_bf16(d, ah[mt], bh[sub], bh[sub + 2]);
                        mma_bf16(d, ah[mt], bl[sub], bl[sub + 2]);
                        mma_bf16(d, al[mt], bh[sub], bh[sub + 2]);
                    }
                }
            }
        }
        __syncthreads();
    }

    int g = lane >> 2, tg = lane & 3;
    #pragma unroll
    for (int mt = 0; mt < 2; mt++) {
        int r0g = row0 + wr * 32 + mt * 16 + g;
        #pragma unroll
        for (int n8 = 0; n8 < 8; n8++) {
            int gc = col0 + wc * 64 + n8 * 8 + tg * 2;
            float* d = acc[mt][n8];
            #pragma unroll
            for (int e = 0; e < 4; e++) {
                int rr = r0g + ((e >= 2) ? 8 : 0);
                int cc_ = gc + (e & 1);
                if (cc_ < N) {
                    float v = d[e];
                    if (BIAS) v += bias[cc_];
                    if (GELU) v = 0.5f * v * (1.0f + erff(v * 0.7071067811865475f));
                    if (RES)  v += res[(size_t)rr * N + cc_];
                    size_t idx = (size_t)rr * N + cc_;
                    if (OUTHL) {
                        __nv_bfloat16 hv = __float2bfloat16(v);
                        Chi[idx] = hv;
                        Clo[idx] = __float2bfloat16(v - __bfloat162float(hv));
                    } else {
                        C[idx] = v;
                    }
                }
            }
        }
    }
}

// ---------------- HMMA fp16 GEMM (LM head) ----------------
#define H_A      0
#define H_B      10240
#define H_STAGE  20480
#define GSMEMH   (2 * H_STAGE)

__global__ void __launch_bounds__(256, 2)
gemmh_kernel(const __half* __restrict__ A, const __half* __restrict__ B,
             float* __restrict__ C, int M, int N, int K) {
    extern __shared__ char smem[];
    uint32_t sb = smem_u32(smem);
    int tid = threadIdx.x;
    int lane = tid & 31, wid = tid >> 5;
    int wr = wid >> 1, wc = wid & 1;
    int row0 = blockIdx.y * 128, col0 = blockIdx.x * 128;

    const char* pA = (const char*)A;
    const char* pB = (const char*)B;

    float acc[2][8][4];
    #pragma unroll
    for (int a = 0; a < 2; a++)
        #pragma unroll
        for (int b = 0; b < 8; b++)
            #pragma unroll
            for (int e = 0; e < 4; e++) acc[a][b][e] = 0.f;

    int nc = K / 32;
    size_t Kb = (size_t)K * 2;
    int l_row0 = tid >> 2;
    int l_p    = tid & 3;

    auto load_tile = [&](int c) {
        uint32_t s = sb + (uint32_t)(c & 1) * H_STAGE;
        size_t kb = (size_t)c * 64;
        #pragma unroll
        for (int i = 0; i < 2; i++) {
            int row = l_row0 + i * 64;
            uint32_t so = (uint32_t)row * TSTRIDE + (uint32_t)l_p * 16;
            size_t ao = (size_t)(row0 + row) * Kb + kb + (size_t)l_p * 16;
            cp16(s + H_A + so, pA + ao, 16);
            int nr = col0 + row;
            int v = (nr < N) ? 16 : 0;
            size_t bo = (size_t)((nr < N) ? nr : 0) * Kb + kb + (size_t)l_p * 16;
            cp16(s + H_B + so, pB + bo, v);
        }
        cp_commit();
    };

    load_tile(0);

    int lr = lane & 15;
    int lh = (lane >> 4) * 16;

    for (int c = 0; c < nc; c++) {
        if (c + 1 < nc) {
            load_tile(c + 1);
            asm volatile("cp.async.wait_group 1;" ::: "memory");
        } else {
            asm volatile("cp.async.wait_group 0;" ::: "memory");
        }
        __syncthreads();

        uint32_t s = sb + (uint32_t)(c & 1) * H_STAGE;
        #pragma unroll
        for (int ks = 0; ks < 2; ks++) {
            uint32_t ko = ks * 32;
            uint32_t ah[2][4];
            #pragma unroll
            for (int mt = 0; mt < 2; mt++) {
                uint32_t ad = s + H_A +
                              (uint32_t)(wr * 32 + mt * 16 + lr) * TSTRIDE + ko + lh;
                ldsm4(ah[mt], ad);
            }
            #pragma unroll
            for (int nt = 0; nt < 4; nt++) {
                uint32_t bd = s + H_B +
                              (uint32_t)(wc * 64 + nt * 16 + lr) * TSTRIDE + ko + lh;
                uint32_t bf[4];
                ldsm4(bf, bd);
                #pragma unroll
                for (int mt = 0; mt < 2; mt++) {
                    #pragma unroll
                    for (int sub = 0; sub < 2; sub++)
                        mma_fp16(acc[mt][nt * 2 + sub], ah[mt], bf[sub], bf[sub + 2]);
                }
            }
        }
        __syncthreads();
    }

    int g = lane >> 2, tg = lane & 3;
    #pragma unroll
    for (int mt = 0; mt < 2; mt++) {
        int r0g = row0 + wr * 32 + mt * 16 + g;
        #pragma unroll
        for (int n8 = 0; n8 < 8; n8++) {
            int gc = col0 + wc * 64 + n8 * 8 + tg * 2;
            float* d = acc[mt][n8];
            #pragma unroll
            for (int e = 0; e < 4; e++) {
                int rr = r0g + ((e >= 2) ? 8 : 0);
                int cc_ = gc + (e & 1);
                if (cc_ < N) C[(size_t)rr * N + cc_] = d[e];
            }
        }
    }
}

// ---------------- host orchestration ----------------
static void conv_wT(const float* W, __nv_bfloat16* hi, __nv_bfloat16* lo, int K, int N) {
    conv_wt_kernel<<<dim3(N / 32, K / 32), dim3(32, 8)>>>(W, hi, lo, K, N);
}

template<bool BIAS, bool GELU, bool RES, bool OUTHL>
static void gemm3(const __nv_bfloat16* ahi, const __nv_bfloat16* alo,
                  const __nv_bfloat16* bhi, const __nv_bfloat16* blo,
                  const float* bias, const float* res,
                  float* C, __nv_bfloat16* Chi, __nv_bfloat16* Clo,
                  int M, int N, int K) {
    dim3 grid((N + 127) / 128, M / 128);
    gemm3_kernel<BIAS, GELU, RES, OUTHL><<<grid, 256, GSMEM>>>(
        ahi, alo, bhi, blo, bias, res, C, Chi, Clo, M, N, K);
}

extern "C" void kernel_launch(void* const* d_in, const int* in_sizes, int n_in,
                              void* d_out, int out_size) {
    const int*   inp   = (const int*)  d_in[0];
    const float* wte   = (const float*)d_in[1];
    const float* wpe   = (const float*)d_in[2];
    const float* ln1_g = (const float*)d_in[3];
    const float* ln1_b = (const float*)d_in[4];
    const float* wqkv  = (const float*)d_in[5];
    const float* bqkv  = (const float*)d_in[6];
    const float* wout  = (const float*)d_in[7];
    const float* bout  = (const float*)d_in[8];
    const float* ln2_g = (const float*)d_in[9];
    const float* ln2_b = (const float*)d_in[10];
    const float* wfc1  = (const float*)d_in[11];
    const float* bfc1  = (const float*)d_in[12];
    const float* wfc2  = (const float*)d_in[13];
    const float* bfc2  = (const float*)d_in[14];
    const float* lnf_g = (const float*)d_in[15];
    const float* lnf_b = (const float*)d_in[16];
    float* logits = (float*)d_out;

    float *x;
    __nv_bfloat16 *qhi, *qlo, *ahi, *alo, *fhi, *flo, *whi, *wlo;
    __half *ahf, *tef;
    cudaGetSymbolAddress((void**)&x,   g_x);
    cudaGetSymbolAddress((void**)&qhi, g_qhi);
    cudaGetSymbolAddress((void**)&qlo, g_qlo);
    cudaGetSymbolAddress((void**)&ahi, g_ahi);
    cudaGetSymbolAddress((void**)&alo, g_alo);
    cudaGetSymbolAddress((void**)&fhi, g_fhi);
    cudaGetSymbolAddress((void**)&flo, g_flo);
    cudaGetSymbolAddress((void**)&whi, g_whi);
    cudaGetSymbolAddress((void**)&wlo, g_wlo);
    cudaGetSymbolAddress((void**)&ahf, g_ahf);
    cudaGetSymbolAddress((void**)&tef, g_tef);

    cudaFuncSetAttribute(gemm3_kernel<true,  false, false, true >, cudaFuncAttributeMaxDynamicSharedMemorySize, GSMEM);
    cudaFuncSetAttribute(gemm3_kernel<true,  false, true,  false>, cudaFuncAttributeMaxDynamicSharedMemorySize, GSMEM);
    cudaFuncSetAttribute(gemm3_kernel<true,  true,  false, true >, cudaFuncAttributeMaxDynamicSharedMemorySize, GSMEM);
    cudaFuncSetAttribute(gemmh_kernel, cudaFuncAttributeMaxDynamicSharedMemorySize, GSMEMH);
    cudaFuncSetAttribute(fattn_kernel, cudaFuncAttributeMaxDynamicSharedMemorySize, FA_SMEM);

    embed_kernel<<<(BT * CC + 255) / 256, 256>>>(inp, wte, wpe, x);

    for (int l = 0; l < NL; l++) {
        const float* g1  = ln1_g + (size_t)l * CC;
        const float* b1  = ln1_b + (size_t)l * CC;
        const float* wq  = wqkv  + (size_t)l * CC * C3;
        const float* bq  = bqkv  + (size_t)l * C3;
        const float* wo  = wout  + (size_t)l * CC * CC;
        const float* bo  = bout  + (size_t)l * CC;
        const float* g2  = ln2_g + (size_t)l * CC;
        const float* b2  = ln2_b + (size_t)l * CC;
        const float* w1  = wfc1  + (size_t)l * CC * C4;
        const float* bb1 = bfc1  + (size_t)l * C4;
        const float* w2  = wfc2  + (size_t)l * C4 * CC;
        const float* bb2 = bfc2  + (size_t)l * CC;

        ln_hl_kernel<<<BT / 8, 256>>>(x, g1, b1, ahi, alo);
        conv_wT(wq, whi, wlo, CC, C3);
        gemm3<true, false, false, true>(ahi, alo, whi, wlo, bq, nullptr,
                                        nullptr, qhi, qlo, BT, C3, CC);

        fattn_kernel<<<dim3(16, BB * HH), 128, FA_SMEM>>>(qhi, qlo, ahi, alo);

        conv_wT(wo, whi, wlo, CC, CC);
        gemm3<true, false, true, false>(ahi, alo, whi, wlo, bo, x,
                                        x, nullptr, nullptr, BT, CC, CC);

        ln_hl_kernel<<<BT / 8, 256>>>(x, g2, b2, ahi, alo);
        conv_wT(w1, whi, wlo, CC, C4);
        gemm3<true, true, false, true>(ahi, alo, whi, wlo, bb1, nullptr,
                                       nullptr, fhi, flo, BT, C4, CC);

        conv_wT(w2, whi, wlo, C4, CC);
        gemm3<true, false, true, false>(fhi, flo, whi, wlo, bb2, x,
                                        x, nullptr, nullptr, BT, CC, C4);
    }

    ln_hf_kernel<<<BT / 8, 256>>>(x, lnf_g, lnf_b, ahf);
    conv_hf_kernel<<<(unsigned)(((size_t)VV * CC + 255) / 256), 256>>>(
        wte, tef, (size_t)VV * CC);
    {
        dim3 grid((VV + 127) / 128, BT / 128);
        gemmh_kernel<<<grid, 256, GSMEMH>>>(ahf, tef, logits, BT, VV, CC);
    }
}

// round 10
// speedup vs baseline: 1.7838x; 1.1095x over previous
#include <cuda_runtime.h>
#include <cuda_bf16.h>
#include <cuda_fp16.h>
#include <math.h>
#include <stdint.h>

// ---------------- problem constants ----------------
#define NL   12
#define BB   4
#define TT   1024
#define CC   768
#define HH   12
#define HS   64
#define VV   50257
#define BT   (BB * TT)
#define C3   (3 * CC)
#define C4   (4 * CC)
#define SCALE 0.125f

// ---------------- device scratch ----------------
__device__ float g_x[BT * CC];
__device__ __nv_bfloat16 g_qhi[BT * C3];
__device__ __nv_bfloat16 g_qlo[BT * C3];
__device__ __nv_bfloat16 g_ahi[BT * CC];
__device__ __nv_bfloat16 g_alo[BT * CC];
__device__ __nv_bfloat16 g_fhi[BT * C4];
__device__ __nv_bfloat16 g_flo[BT * C4];
__device__ __nv_bfloat16 g_whi[C4 * CC];
__device__ __nv_bfloat16 g_wlo[C4 * CC];
__device__ __half g_ahf[BT * CC];
__device__ __half g_tef[(size_t)VV * CC];

// ---------------- PTX helpers ----------------
__device__ __forceinline__ uint32_t smem_u32(const void* p) {
    uint32_t a;
    asm("{ .reg .u64 t; cvta.to.shared.u64 t, %1; cvt.u32.u64 %0, t; }" : "=r"(a) : "l"(p));
    return a;
}
__device__ __forceinline__ void cp16(uint32_t dst, const void* src, int sz) {
    asm volatile("cp.async.ca.shared.global [%0], [%1], 16, %2;"
                 :: "r"(dst), "l"(src), "r"(sz) : "memory");
}
__device__ __forceinline__ void cp_commit() {
    asm volatile("cp.async.commit_group;" ::: "memory");
}
__device__ __forceinline__ void ldsm4(uint32_t* r, uint32_t a) {
    asm volatile("ldmatrix.sync.aligned.m8n8.x4.shared.b16 {%0,%1,%2,%3}, [%4];"
                 : "=r"(r[0]), "=r"(r[1]), "=r"(r[2]), "=r"(r[3]) : "r"(a));
}
__device__ __forceinline__ void ldsm4t(uint32_t* r, uint32_t a) {
    asm volatile("ldmatrix.sync.aligned.m8n8.x4.trans.shared.b16 {%0,%1,%2,%3}, [%4];"
                 : "=r"(r[0]), "=r"(r[1]), "=r"(r[2]), "=r"(r[3]) : "r"(a));
}
__device__ __forceinline__ void mma_bf16(float* d, const uint32_t* a,
                                         uint32_t b0, uint32_t b1) {
    asm volatile(
        "mma.sync.aligned.m16n8k16.row.col.f32.bf16.bf16.f32 "
        "{%0,%1,%2,%3}, {%4,%5,%6,%7}, {%8,%9}, {%0,%1,%2,%3};"
        : "+f"(d[0]), "+f"(d[1]), "+f"(d[2]), "+f"(d[3])
        : "r"(a[0]), "r"(a[1]), "r"(a[2]), "r"(a[3]), "r"(b0), "r"(b1));
}
__device__ __forceinline__ void mma_fp16(float* d, const uint32_t* a,
                                         uint32_t b0, uint32_t b1) {
    asm volatile(
        "mma.sync.aligned.m16n8k16.row.col.f32.f16.f16.f32 "
        "{%0,%1,%2,%3}, {%4,%5,%6,%7}, {%8,%9}, {%0,%1,%2,%3};"
        : "+f"(d[0]), "+f"(d[1]), "+f"(d[2]), "+f"(d[3])
        : "r"(a[0]), "r"(a[1]), "r"(a[2]), "r"(a[3]), "r"(b0), "r"(b1));
}
__device__ __forceinline__ uint32_t packbf(float a, float b) {
    __nv_bfloat162 t = __floats2bfloat162_rn(a, b);
    return *reinterpret_cast<uint32_t*>(&t);
}
__device__ __forceinline__ float bfhi(float v) {
    return __bfloat162float(__float2bfloat16(v));
}

// ---------------- embedding ----------------
__global__ void embed_kernel(const int* __restrict__ inp,
                             const float* __restrict__ wte,
                             const float* __restrict__ wpe,
                             float* __restrict__ x) {
    int i = blockIdx.x * blockDim.x + threadIdx.x;
    if (i >= BT * CC) return;
    int c = i % CC;
    int bt = i / CC;
    int t = bt % TT;
    int tok = inp[bt];
    x[i] = wte[(size_t)tok * CC + c] + wpe[(size_t)t * CC + c];
}

// ---------------- layernorm (warp per row) -> bf16 hi/lo ----------------
__global__ void __launch_bounds__(256)
ln_hl_kernel(const float* __restrict__ in,
             const float* __restrict__ g,
             const float* __restrict__ b,
             __nv_bfloat16* __restrict__ hi,
             __nv_bfloat16* __restrict__ lo) {
    int row = blockIdx.x * 8 + (threadIdx.x >> 5);
    int lane = threadIdx.x & 31;
    const float4* r4 = (const float4*)(in + (size_t)row * CC);

    float4 v[6];
    float s = 0.f;
    #pragma unroll
    for (int i = 0; i < 6; i++) {
        v[i] = r4[lane + i * 32];
        s += v[i].x + v[i].y + v[i].z + v[i].w;
    }
    #pragma unroll
    for (int o = 16; o > 0; o >>= 1) s += __shfl_xor_sync(0xffffffffu, s, o);
    float mu = s / CC;

    float sq = 0.f;
    #pragma unroll
    for (int i = 0; i < 6; i++) {
        float dx = v[i].x - mu, dy = v[i].y - mu, dz = v[i].z - mu, dw = v[i].w - mu;
        sq += dx * dx + dy * dy + dz * dz + dw * dw;
    }
    #pragma unroll
    for (int o = 16; o > 0; o >>= 1) sq += __shfl_xor_sync(0xffffffffu, sq, o);
    float rstd = rsqrtf(sq / CC + 1e-5f);

    const float4* g4 = (const float4*)g;
    const float4* b4 = (const float4*)b;
    uint2* h2 = (uint2*)(hi + (size_t)row * CC);
    uint2* l2 = (uint2*)(lo + (size_t)row * CC);
    #pragma unroll
    for (int i = 0; i < 6; i++) {
        int f4 = lane + i * 32;
        float4 gv = g4[f4], bv = b4[f4];
        float o0 = (v[i].x - mu) * rstd * gv.x + bv.x;
        float o1 = (v[i].y - mu) * rstd * gv.y + bv.y;
        float o2 = (v[i].z - mu) * rstd * gv.z + bv.z;
        float o3 = (v[i].w - mu) * rstd * gv.w + bv.w;
        uint2 hw, lw;
        hw.x = packbf(o0, o1); hw.y = packbf(o2, o3);
        lw.x = packbf(o0 - bfhi(o0), o1 - bfhi(o1));
        lw.y = packbf(o2 - bfhi(o2), o3 - bfhi(o3));
        h2[f4] = hw;
        l2[f4] = lw;
    }
}

// ---------------- final layernorm (warp per row) -> fp16 ----------------
__global__ void __launch_bounds__(256)
ln_hf_kernel(const float* __restrict__ in,
             const float* __restrict__ g,
             const float* __restrict__ b,
             __half* __restrict__ out) {
    int row = blockIdx.x * 8 + (threadIdx.x >> 5);
    int lane = threadIdx.x & 31;
    const float4* r4 = (const float4*)(in + (size_t)row * CC);

    float4 v[6];
    float s = 0.f;
    #pragma unroll
    for (int i = 0; i < 6; i++) {
        v[i] = r4[lane + i * 32];
        s += v[i].x + v[i].y + v[i].z + v[i].w;
    }
    #pragma unroll
    for (int o = 16; o > 0; o >>= 1) s += __shfl_xor_sync(0xffffffffu, s, o);
    float mu = s / CC;

    float sq = 0.f;
    #pragma unroll
    for (int i = 0; i < 6; i++) {
        float dx = v[i].x - mu, dy = v[i].y - mu, dz = v[i].z - mu, dw = v[i].w - mu;
        sq += dx * dx + dy * dy + dz * dz + dw * dw;
    }
    #pragma unroll
    for (int o = 16; o > 0; o >>= 1) sq += __shfl_xor_sync(0xffffffffu, sq, o);
    float rstd = rsqrtf(sq / CC + 1e-5f);

    const float4* g4 = (const float4*)g;
    const float4* b4 = (const float4*)b;
    uint2* o2p = (uint2*)(out + (size_t)row * CC);
    #pragma unroll
    for (int i = 0; i < 6; i++) {
        int f4 = lane + i * 32;
        float4 gv = g4[f4], bv = b4[f4];
        float o0 = (v[i].x - mu) * rstd * gv.x + bv.x;
        float o1 = (v[i].y - mu) * rstd * gv.y + bv.y;
        float o2 = (v[i].z - mu) * rstd * gv.z + bv.z;
        float o3 = (v[i].w - mu) * rstd * gv.w + bv.w;
        __half2 p0 = __floats2half2_rn(o0, o1);
        __half2 p1 = __floats2half2_rn(o2, o3);
        uint2 w;
        w.x = *(uint32_t*)&p0; w.y = *(uint32_t*)&p1;
        o2p[f4] = w;
    }
}

// ---------------- flash attention (pipelined, trans-V, full bf16x3) -------
#define FA_STRIDE 144
#define FA_TILE   (64 * FA_STRIDE)
#define FA_KV0    (2 * FA_TILE)
#define FA_STAGE  (4 * FA_TILE)
#define FA_SMEM   (2 * FA_TILE + 2 * FA_STAGE)

__global__ void __launch_bounds__(128, 2)
fattn_kernel(const __nv_bfloat16* __restrict__ qhi,
             const __nv_bfloat16* __restrict__ qlo,
             __nv_bfloat16* __restrict__ ohi,
             __nv_bfloat16* __restrict__ olo) {
    extern __shared__ char fs[];
    uint32_t sb = smem_u32(fs);
    int qt = 15 - blockIdx.x;
    int bh = blockIdx.y;
    int h = bh % HH, b = bh / HH;
    int tid = threadIdx.x, lane = tid & 31, w = tid >> 5;
    int q0 = qt * 64;
    size_t boff = (size_t)b * TT * C3 + (size_t)h * 3 * HS;
    const __nv_bfloat16* bhp = qhi + boff;
    const __nv_bfloat16* blp = qlo + boff;

    int lrow = tid >> 1, lc = (tid & 1) * 32;
    uint32_t lso = (uint32_t)lrow * FA_STRIDE + (uint32_t)lc * 2;

    auto load_kv = [&](int kt, int s) {
        uint32_t base = sb + FA_KV0 + (uint32_t)s * FA_STAGE;
        size_t krow = (size_t)(kt * 64 + lrow) * C3 + lc;
        const char* kh = (const char*)(bhp + krow + HS);
        const char* kl = (const char*)(blp + krow + HS);
        const char* vh = (const char*)(bhp + krow + 2 * HS);
        const char* vl = (const char*)(blp + krow + 2 * HS);
        #pragma unroll
        for (int i = 0; i < 4; i++) {
            cp16(base + 0 * FA_TILE + lso + i * 16, kh + i * 16, 16);
            cp16(base + 1 * FA_TILE + lso + i * 16, kl + i * 16, 16);
            cp16(base + 2 * FA_TILE + lso + i * 16, vh + i * 16, 16);
            cp16(base + 3 * FA_TILE + lso + i * 16, vl + i * 16, 16);
        }
        cp_commit();
    };

    {
        const uint4* sh = (const uint4*)(bhp + (size_t)(q0 + lrow) * C3 + lc);
        const uint4* sl = (const uint4*)(blp + (size_t)(q0 + lrow) * C3 + lc);
        uint4* dh = (uint4*)(fs + 0 * FA_TILE + lrow * FA_STRIDE + lc * 2);
        uint4* dl = (uint4*)(fs + 1 * FA_TILE + lrow * FA_STRIDE + lc * 2);
        #pragma unroll
        for (int i = 0; i < 4; i++) { dh[i] = sh[i]; dl[i] = sl[i]; }
    }
    load_kv(0, 0);
    __syncthreads();

    int lr = lane & 15, lh = (lane >> 4) * 16;
    uint32_t qh[4][4], ql[4][4];
    #pragma unroll
    for (int kk = 0; kk < 4; kk++) {
        uint32_t ad = sb + 0 * FA_TILE + (uint32_t)(w * 16 + lr) * FA_STRIDE + kk * 32 + lh;
        ldsm4(qh[kk], ad);
        ldsm4(ql[kk], ad + FA_TILE);
    }

    uint32_t vrow_l = (uint32_t)((lane & 7) + ((lane >> 4) << 3));
    uint32_t vcol_l = (uint32_t)(((lane >> 3) & 1) * 16);

    int g = lane >> 2, tg = lane & 3;
    int r0 = q0 + w * 16 + g;
    float m0 = -1e30f, m1 = -1e30f, l0 = 0.f, l1 = 0.f;
    float O[8][4];
    #pragma unroll
    for (int f = 0; f < 8; f++)
        #pragma unroll
        for (int e = 0; e < 4; e++) O[f][e] = 0.f;

    for (int kt = 0; kt <= qt; kt++) {
        int buf = kt & 1;
        if (kt + 1 <= qt) {
            load_kv(kt + 1, buf ^ 1);
            asm volatile("cp.async.wait_group 1;" ::: "memory");
        } else {
            asm volatile("cp.async.wait_group 0;" ::: "memory");
        }
        __syncthreads();

        uint32_t stage = sb + FA_KV0 + (uint32_t)buf * FA_STAGE;

        float S[8][4];
        #pragma unroll
        for (int f = 0; f < 8; f++)
            #pragma unroll
            for (int e = 0; e < 4; e++) S[f][e] = 0.f;

        #pragma unroll
        for (int kk = 0; kk < 4; kk++) {
            #pragma unroll
            for (int nt = 0; nt < 4; nt++) {
                uint32_t bd = stage + (uint32_t)(nt * 16 + lr) * FA_STRIDE + kk * 32 + lh;
                uint32_t bhf[4], blf[4];
                ldsm4(bhf, bd);
                ldsm4(blf, bd + FA_TILE);
                #pragma unroll
                for (int sub = 0; sub < 2; sub++) {
                    float* d = S[nt * 2 + sub];
                    mma_bf16(d, qh[kk], bhf[sub], bhf[sub + 2]);
                    mma_bf16(d, qh[kk], blf[sub], blf[sub + 2]);
                    mma_bf16(d, ql[kk], bhf[sub], bhf[sub + 2]);
                }
            }
        }

        #pragma unroll
        for (int f = 0; f < 8; f++)
            #pragma unroll
            for (int e = 0; e < 4; e++) S[f][e] *= SCALE;
        if (kt == qt) {
            #pragma unroll
            for (int f = 0; f < 8; f++) {
                int colb = kt * 64 + f * 8 + tg * 2;
                if (colb     > r0)     S[f][0] = -1e30f;
                if (colb + 1 > r0)     S[f][1] = -1e30f;
                if (colb     > r0 + 8) S[f][2] = -1e30f;
                if (colb + 1 > r0 + 8) S[f][3] = -1e30f;
            }
        }

        float mx0 = -1e30f, mx1 = -1e30f;
        #pragma unroll
        for (int f = 0; f < 8; f++) {
            mx0 = fmaxf(mx0, fmaxf(S[f][0], S[f][1]));
            mx1 = fmaxf(mx1, fmaxf(S[f][2], S[f][3]));
        }
        mx0 = fmaxf(mx0, __shfl_xor_sync(0xffffffffu, mx0, 1));
        mx0 = fmaxf(mx0, __shfl_xor_sync(0xffffffffu, mx0, 2));
        mx1 = fmaxf(mx1, __shfl_xor_sync(0xffffffffu, mx1, 1));
        mx1 = fmaxf(mx1, __shfl_xor_sync(0xffffffffu, mx1, 2));

        float mn0 = fmaxf(m0, mx0), mn1 = fmaxf(m1, mx1);
        float sc0 = __expf(m0 - mn0), sc1 = __expf(m1 - mn1);
        m0 = mn0; m1 = mn1;
        l0 *= sc0; l1 *= sc1;
        #pragma unroll
        for (int f = 0; f < 8; f++) {
            O[f][0] *= sc0; O[f][1] *= sc0;
            O[f][2] *= sc1; O[f][3] *= sc1;
        }

        float ps0 = 0.f, ps1 = 0.f;
        #pragma unroll
        for (int f = 0; f < 8; f++) {
            S[f][0] = __expf(S[f][0] - m0);
            S[f][1] = __expf(S[f][1] - m0);
            S[f][2] = __expf(S[f][2] - m1);
            S[f][3] = __expf(S[f][3] - m1);
            ps0 += S[f][0] + S[f][1];
            ps1 += S[f][2] + S[f][3];
        }
        ps0 += __shfl_xor_sync(0xffffffffu, ps0, 1);
        ps0 += __shfl_xor_sync(0xffffffffu, ps0, 2);
        ps1 += __shfl_xor_sync(0xffffffffu, ps1, 1);
        ps1 += __shfl_xor_sync(0xffffffffu, ps1, 2);
        l0 += ps0; l1 += ps1;

        uint32_t ph[4][4], pl[4][4];
        #pragma unroll
        for (int kk = 0; kk < 4; kk++) {
            float* A0 = S[2 * kk];
            float* A1 = S[2 * kk + 1];
            ph[kk][0] = packbf(A0[0], A0[1]);
            ph[kk][1] = packbf(A0[2], A0[3]);
            ph[kk][2] = packbf(A1[0], A1[1]);
            ph[kk][3] = packbf(A1[2], A1[3]);
            pl[kk][0] = packbf(A0[0] - bfhi(A0[0]), A0[1] - bfhi(A0[1]));
            pl[kk][1] = packbf(A0[2] - bfhi(A0[2]), A0[3] - bfhi(A0[3]));
            pl[kk][2] = packbf(A1[0] - bfhi(A1[0]), A1[1] - bfhi(A1[1]));
            pl[kk][3] = packbf(A1[2] - bfhi(A1[2]), A1[3] - bfhi(A1[3]));
        }

        #pragma unroll
        for (int kk = 0; kk < 4; kk++) {
            uint32_t vr = (uint32_t)(kk * 16) + vrow_l;
            #pragma unroll
            for (int nt = 0; nt < 4; nt++) {
                uint32_t bd = stage + 2 * FA_TILE + vr * FA_STRIDE + (uint32_t)(nt * 32) + vcol_l;
                uint32_t bhf[4], blf[4];
                ldsm4t(bhf, bd);
                ldsm4t(blf, bd + FA_TILE);
                #pragma unroll
                for (int sub = 0; sub < 2; sub++) {
                    float* d = O[nt * 2 + sub];
                    mma_bf16(d, ph[kk], bhf[sub], bhf[sub + 2]);
                    mma_bf16(d, ph[kk], blf[sub], blf[sub + 2]);
                    mma_bf16(d, pl[kk], bhf[sub], bhf[sub + 2]);
                }
            }
        }
        __syncthreads();
    }

    float inv0 = 1.f / l0, inv1 = 1.f / l1;
    #pragma unroll
    for (int f = 0; f < 8; f++) {
        int col = h * HS + f * 8 + tg * 2;
        size_t i0 = ((size_t)(b * TT + r0)) * CC + col;
        size_t i1 = i0 + (size_t)8 * CC;
        float v00 = O[f][0] * inv0, v01 = O[f][1] * inv0;
        float v10 = O[f][2] * inv1, v11 = O[f][3] * inv1;
        *(uint32_t*)(ohi + i0) = packbf(v00, v01);
        *(uint32_t*)(olo + i0) = packbf(v00 - bfhi(v00), v01 - bfhi(v01));
        *(uint32_t*)(ohi + i1) = packbf(v10, v11);
        *(uint32_t*)(olo + i1) = packbf(v10 - bfhi(v10), v11 - bfhi(v11));
    }
}

// ---------------- weight transpose + hi/lo split ----------------
__global__ void conv_wt_kernel(const float* __restrict__ W,
                               __nv_bfloat16* __restrict__ hi,
                               __nv_bfloat16* __restrict__ lo,
                               int K, int N) {
    __shared__ float ts[32][33];
    int k0 = blockIdx.y * 32, n0 = blockIdx.x * 32;
    int tx = threadIdx.x, ty = threadIdx.y;
    #pragma unroll
    for (int i = 0; i < 32; i += 8)
        ts[ty + i][tx] = W[(size_t)(k0 + ty + i) * N + n0 + tx];
    __syncthreads();
    #pragma unroll
    for (int i = 0; i < 32; i += 8) {
        float v = ts[tx][ty + i];
        size_t o = (size_t)(n0 + ty + i) * K + k0 + tx;
        __nv_bfloat16 h = __float2bfloat16(v);
        hi[o] = h;
        lo[o] = __float2bfloat16(v - __bfloat162float(h));
    }
}

// ---------------- wte -> fp16 ----------------
__global__ void conv_hf_kernel(const float* __restrict__ x,
                               __half* __restrict__ out, size_t n) {
    size_t i = (size_t)blockIdx.x * blockDim.x + threadIdx.x;
    if (i < n) out[i] = __float2half(x[i]);
}

// ---------------- HMMA bf16x3 GEMM (8 warps, 32x64 warp tile) ----------------
#define TSTRIDE  80
#define T_A_HI   0
#define T_A_LO   10240
#define T_B_HI   20480
#define T_B_LO   30720
#define T_STAGE  40960
#define GSMEM    (2 * T_STAGE)

__device__ __forceinline__ float gelu_f(float v) {
    return 0.5f * v * (1.0f + erff(v * 0.7071067811865475f));
}

template<bool BIAS, bool GELU, bool RES, bool OUTHL>
__global__ void __launch_bounds__(256, 2)
gemm3_kernel(const __nv_bfloat16* __restrict__ Ahi, const __nv_bfloat16* __restrict__ Alo,
             const __nv_bfloat16* __restrict__ Bhi, const __nv_bfloat16* __restrict__ Blo,
             const float* __restrict__ bias, const float* __restrict__ res,
             float* __restrict__ C,
             __nv_bfloat16* __restrict__ Chi, __nv_bfloat16* __restrict__ Clo,
             int M, int N, int K) {
    extern __shared__ char smem[];
    uint32_t sb = smem_u32(smem);
    int tid = threadIdx.x;
    int lane = tid & 31, wid = tid >> 5;
    int wr = wid >> 1, wc = wid & 1;
    int row0 = blockIdx.y * 128, col0 = blockIdx.x * 128;

    const char* pAhi = (const char*)Ahi;
    const char* pAlo = (const char*)Alo;
    const char* pBhi = (const char*)Bhi;
    const char* pBlo = (const char*)Blo;

    float acc[2][8][4];
    #pragma unroll
    for (int a = 0; a < 2; a++)
        #pragma unroll
        for (int b = 0; b < 8; b++)
            #pragma unroll
            for (int e = 0; e < 4; e++) acc[a][b][e] = 0.f;

    int nc = K / 32;
    size_t Kb = (size_t)K * 2;
    int l_row0 = tid >> 2;
    int l_p    = tid & 3;

    auto load_tile = [&](int c) {
        uint32_t s = sb + (uint32_t)(c & 1) * T_STAGE;
        size_t kb = (size_t)c * 64;
        #pragma unroll
        for (int i = 0; i < 2; i++) {
            int row = l_row0 + i * 64;
            uint32_t so = (uint32_t)row * TSTRIDE + (uint32_t)l_p * 16;
            size_t ao = (size_t)(row0 + row) * Kb + kb + (size_t)l_p * 16;
            cp16(s + T_A_HI + so, pAhi + ao, 16);
            cp16(s + T_A_LO + so, pAlo + ao, 16);
            int nr = col0 + row;
            int v = (nr < N) ? 16 : 0;
            size_t bo = (size_t)((nr < N) ? nr : 0) * Kb + kb + (size_t)l_p * 16;
            cp16(s + T_B_HI + so, pBhi + bo, v);
            cp16(s + T_B_LO + so, pBlo + bo, v);
        }
        cp_commit();
    };

    load_tile(0);

    int lr = lane & 15;
    int lh = (lane >> 4) * 16;

    for (int c = 0; c < nc; c++) {
        if (c + 1 < nc) {
            load_tile(c + 1);
            asm volatile("cp.async.wait_group 1;" ::: "memory");
        } else {
            asm volatile("cp.async.wait_group 0;" ::: "memory");
        }
        __syncthreads();

        uint32_t s = sb + (uint32_t)(c & 1) * T_STAGE;
        #pragma unroll
        for (int ks = 0; ks < 2; ks++) {
            uint32_t ko = ks * 32;
            uint32_t ah[2][4], al[2][4];
            #pragma unroll
            for (int mt = 0; mt < 2; mt++) {
                uint32_t ad = s + T_A_HI +
                              (uint32_t)(wr * 32 + mt * 16 + lr) * TSTRIDE + ko + lh;
                ldsm4(ah[mt], ad);
                ldsm4(al[mt], ad + (T_A_LO - T_A_HI));
            }
            #pragma unroll
            for (int nt = 0; nt < 4; nt++) {
                uint32_t bd = s + T_B_HI +
                              (uint32_t)(wc * 64 + nt * 16 + lr) * TSTRIDE + ko + lh;
                uint32_t bh[4], bl[4];
                ldsm4(bh, bd);
                ldsm4(bl, bd + (T_B_LO - T_B_HI));
                #pragma unroll
                for (int mt = 0; mt < 2; mt++) {
                    #pragma unroll
                    for (int sub = 0; sub < 2; sub++) {
                        float* d = acc[mt][nt * 2 + sub];
                        mma_bf16(d, ah[mt], bh[sub], bh[sub + 2]);
                        mma_bf16(d, ah[mt], bl[sub], bl[sub + 2]);
                        mma_bf16(d, al[mt], bh[sub], bh[sub + 2]);
                    }
                }
            }
        }
        __syncthreads();
    }

    // ---- vectorized epilogue: paired (gc, gc+1) stores; N even here ----
    int g = lane >> 2, tg = lane & 3;
    #pragma unroll
    for (int mt = 0; mt < 2; mt++) {
        int r0g = row0 + wr * 32 + mt * 16 + g;
        #pragma unroll
        for (int n8 = 0; n8 < 8; n8++) {
            int gc = col0 + wc * 64 + n8 * 8 + tg * 2;
            if (gc + 1 >= N) continue;
            float* d = acc[mt][n8];
            float b0 = 0.f, b1 = 0.f;
            if (BIAS) { b0 = bias[gc]; b1 = bias[gc + 1]; }
            #pragma unroll
            for (int hf = 0; hf < 2; hf++) {
                int rr = r0g + hf * 8;
                float v0 = d[hf * 2] + b0;
                float v1 = d[hf * 2 + 1] + b1;
                if (GELU) { v0 = gelu_f(v0); v1 = gelu_f(v1); }
                size_t idx = (size_t)rr * N + gc;
                if (RES) { v0 += res[idx]; v1 += res[idx + 1]; }
                if (OUTHL) {
                    *(uint32_t*)(Chi + idx) = packbf(v0, v1);
                    *(uint32_t*)(Clo + idx) = packbf(v0 - bfhi(v0), v1 - bfhi(v1));
                } else {
                    float2 t; t.x = v0; t.y = v1;
                    *(float2*)(C + idx) = t;
                }
            }
        }
    }
}

// ---------------- HMMA fp16 GEMM (LM head; N odd -> scalar stores) --------
#define H_A      0
#define H_B      10240
#define H_STAGE  20480
#define GSMEMH   (2 * H_STAGE)

__global__ void __launch_bounds__(256, 2)
gemmh_kernel(const __half* __restrict__ A, const __half* __restrict__ B,
             float* __restrict__ C, int M, int N, int K) {
    extern __shared__ char smem[];
    uint32_t sb = smem_u32(smem);
    int tid = threadIdx.x;
    int lane = tid & 31, wid = tid >> 5;
    int wr = wid >> 1, wc = wid & 1;
    int row0 = blockIdx.y * 128, col0 = blockIdx.x * 128;

    const char* pA = (const char*)A;
    const char* pB = (const char*)B;

    float acc[2][8][4];
    #pragma unroll
    for (int a = 0; a < 2; a++)
        #pragma unroll
        for (int b = 0; b < 8; b++)
            #pragma unroll
            for (int e = 0; e < 4; e++) acc[a][b][e] = 0.f;

    int nc = K / 32;
    size_t Kb = (size_t)K * 2;
    int l_row0 = tid >> 2;
    int l_p    = tid & 3;

    auto load_tile = [&](int c) {
        uint32_t s = sb + (uint32_t)(c & 1) * H_STAGE;
        size_t kb = (size_t)c * 64;
        #pragma unroll
        for (int i = 0; i < 2; i++) {
            int row = l_row0 + i * 64;
            uint32_t so = (uint32_t)row * TSTRIDE + (uint32_t)l_p * 16;
            size_t ao = (size_t)(row0 + row) * Kb + kb + (size_t)l_p * 16;
            cp16(s + H_A + so, pA + ao, 16);
            int nr = col0 + row;
            int v = (nr < N) ? 16 : 0;
            size_t bo = (size_t)((nr < N) ? nr : 0) * Kb + kb + (size_t)l_p * 16;
            cp16(s + H_B + so, pB + bo, v);
        }
        cp_commit();
    };

    load_tile(0);

    int lr = lane & 15;
    int lh = (lane >> 4) * 16;

    for (int c = 0; c < nc; c++) {
        if (c + 1 < nc) {
            load_tile(c + 1);
            asm volatile("cp.async.wait_group 1;" ::: "memory");
        } else {
            asm volatile("cp.async.wait_group 0;" ::: "memory");
        }
        __syncthreads();

        uint32_t s = sb + (uint32_t)(c & 1) * H_STAGE;
        #pragma unroll
        for (int ks = 0; ks < 2; ks++) {
            uint32_t ko = ks * 32;
            uint32_t ah[2][4];
            #pragma unroll
            for (int mt = 0; mt < 2; mt++) {
                uint32_t ad = s + H_A +
                              (uint32_t)(wr * 32 + mt * 16 + lr) * TSTRIDE + ko + lh;
                ldsm4(ah[mt], ad);
            }
            #pragma unroll
            for (int nt = 0; nt < 4; nt++) {
                uint32_t bd = s + H_B +
                              (uint32_t)(wc * 64 + nt * 16 + lr) * TSTRIDE + ko + lh;
                uint32_t bf[4];
                ldsm4(bf, bd);
                #pragma unroll
                for (int mt = 0; mt < 2; mt++) {
                    #pragma unroll
                    for (int sub = 0; sub < 2; sub++)
                        mma_fp16(acc[mt][nt * 2 + sub], ah[mt], bf[sub], bf[sub + 2]);
                }
            }
        }
        __syncthreads();
    }

    int g = lane >> 2, tg = lane & 3;
    #pragma unroll
    for (int mt = 0; mt < 2; mt++) {
        int r0g = row0 + wr * 32 + mt * 16 + g;
        #pragma unroll
        for (int n8 = 0; n8 < 8; n8++) {
            int gc = col0 + wc * 64 + n8 * 8 + tg * 2;
            float* d = acc[mt][n8];
            #pragma unroll
            for (int e = 0; e < 4; e++) {
                int rr = r0g + ((e >= 2) ? 8 : 0);
                int cc_ = gc + (e & 1);
                if (cc_ < N) C[(size_t)rr * N + cc_] = d[e];
            }
        }
    }
}

// ---------------- host orchestration ----------------
static void conv_wT(const float* W, __nv_bfloat16* hi, __nv_bfloat16* lo, int K, int N) {
    conv_wt_kernel<<<dim3(N / 32, K / 32), dim3(32, 8)>>>(W, hi, lo, K, N);
}

template<bool BIAS, bool GELU, bool RES, bool OUTHL>
static void gemm3(const __nv_bfloat16* ahi, const __nv_bfloat16* alo,
                  const __nv_bfloat16* bhi, const __nv_bfloat16* blo,
                  const float* bias, const float* res,
                  float* C, __nv_bfloat16* Chi, __nv_bfloat16* Clo,
                  int M, int N, int K) {
    dim3 grid((N + 127) / 128, M / 128);
    gemm3_kernel<BIAS, GELU, RES, OUTHL><<<grid, 256, GSMEM>>>(
        ahi, alo, bhi, blo, bias, res, C, Chi, Clo, M, N, K);
}

extern "C" void kernel_launch(void* const* d_in, const int* in_sizes, int n_in,
                              void* d_out, int out_size) {
    const int*   inp   = (const int*)  d_in[0];
    const float* wte   = (const float*)d_in[1];
    const float* wpe   = (const float*)d_in[2];
    const float* ln1_g = (const float*)d_in[3];
    const float* ln1_b = (const float*)d_in[4];
    const float* wqkv  = (const float*)d_in[5];
    const float* bqkv  = (const float*)d_in[6];
    const float* wout  = (const float*)d_in[7];
    const float* bout  = (const float*)d_in[8];
    const float* ln2_g = (const float*)d_in[9];
    const float* ln2_b = (const float*)d_in[10];
    const float* wfc1  = (const float*)d_in[11];
    const float* bfc1  = (const float*)d_in[12];
    const float* wfc2  = (const float*)d_in[13];
    const float* bfc2  = (const float*)d_in[14];
    const float* lnf_g = (const float*)d_in[15];
    const float* lnf_b = (const float*)d_in[16];
    float* logits = (float*)d_out;

    float *x;
    __nv_bfloat16 *qhi, *qlo, *ahi, *alo, *fhi, *flo, *whi, *wlo;
    __half *ahf, *tef;
    cudaGetSymbolAddress((void**)&x,   g_x);
    cudaGetSymbolAddress((void**)&qhi, g_qhi);
    cudaGetSymbolAddress((void**)&qlo, g_qlo);
    cudaGetSymbolAddress((void**)&ahi, g_ahi);
    cudaGetSymbolAddress((void**)&alo, g_alo);
    cudaGetSymbolAddress((void**)&fhi, g_fhi);
    cudaGetSymbolAddress((void**)&flo, g_flo);
    cudaGetSymbolAddress((void**)&whi, g_whi);
    cudaGetSymbolAddress((void**)&wlo, g_wlo);
    cudaGetSymbolAddress((void**)&ahf, g_ahf);
    cudaGetSymbolAddress((void**)&tef, g_tef);

    cudaFuncSetAttribute(gemm3_kernel<true,  false, false, true >, cudaFuncAttributeMaxDynamicSharedMemorySize, GSMEM);
    cudaFuncSetAttribute(gemm3_kernel<true,  false, true,  false>, cudaFuncAttributeMaxDynamicSharedMemorySize, GSMEM);
    cudaFuncSetAttribute(gemm3_kernel<true,  true,  false, true >, cudaFuncAttributeMaxDynamicSharedMemorySize, GSMEM);
    cudaFuncSetAttribute(gemmh_kernel, cudaFuncAttributeMaxDynamicSharedMemorySize, GSMEMH);
    cudaFuncSetAttribute(fattn_kernel, cudaFuncAttributeMaxDynamicSharedMemorySize, FA_SMEM);

    embed_kernel<<<(BT * CC + 255) / 256, 256>>>(inp, wte, wpe, x);

    for (int l = 0; l < NL; l++) {
        const float* g1  = ln1_g + (size_t)l * CC;
        const float* b1  = ln1_b + (size_t)l * CC;
        const float* wq  = wqkv  + (size_t)l * CC * C3;
        const float* bq  = bqkv  + (size_t)l * C3;
        const float* wo  = wout  + (size_t)l * CC * CC;
        const float* bo  = bout  + (size_t)l * CC;
        const float* g2  = ln2_g + (size_t)l * CC;
        const float* b2  = ln2_b + (size_t)l * CC;
        const float* w1  = wfc1  + (size_t)l * CC * C4;
        const float* bb1 = bfc1  + (size_t)l * C4;
        const float* w2  = wfc2  + (size_t)l * C4 * CC;
        const float* bb2 = bfc2  + (size_t)l * CC;

        ln_hl_kernel<<<BT / 8, 256>>>(x, g1, b1, ahi, alo);
        conv_wT(wq, whi, wlo, CC, C3);
        gemm3<true, false, false, true>(ahi, alo, whi, wlo, bq, nullptr,
                                        nullptr, qhi, qlo, BT, C3, CC);

        fattn_kernel<<<dim3(16, BB * HH), 128, FA_SMEM>>>(qhi, qlo, ahi, alo);

        conv_wT(wo, whi, wlo, CC, CC);
        gemm3<true, false, true, false>(ahi, alo, whi, wlo, bo, x,
                                        x, nullptr, nullptr, BT, CC, CC);

        ln_hl_kernel<<<BT / 8, 256>>>(x, g2, b2, ahi, alo);
        conv_wT(w1, whi, wlo, CC, C4);
        gemm3<true, true, false, true>(ahi, alo, whi, wlo, bb1, nullptr,
                                       nullptr, fhi, flo, BT, C4, CC);

        conv_wT(w2, whi, wlo, C4, CC);
        gemm3<true, false, true, false>(fhi, flo, whi, wlo, bb2, x,
                                        x, nullptr, nullptr, BT, CC, C4);
    }

    ln_hf_kernel<<<BT / 8, 256>>>(x, lnf_g, lnf_b, ahf);
    conv_hf_kernel<<<(unsigned)(((size_t)VV * CC + 255) / 256), 256>>>(
        wte, tef, (size_t)VV * CC);
    {
        dim3 grid((VV + 127) / 128, BT / 128);
        gemmh_kernel<<<grid, 256, GSMEMH>>>(ahf, tef, logits, BT, VV, CC);
    }
}